// round 1
// baseline (speedup 1.0000x reference)
#include <cuda_runtime.h>
#include <cuda_bf16.h>
#include <math.h>

// ---------------- problem dims ----------------
#define NTOK 4096          // B*T
#define CDIM 1024
#define HN_HEADS 16
#define HD 64
#define LAT 512
#define NEXP 8
#define TOPK 2
#define FDIM 1024
#define FSH 2048           // F * N_SHARED
#define MAXSLOT 9216       // 8192 + 8*64 padding headroom

// ---------------- scratch (device globals: sanctioned workaround) ----------------
__device__ float g_xn [NTOK*CDIM];
__device__ float g_q  [NTOK*CDIM];
__device__ float g_kv [NTOK*LAT];
__device__ float g_k  [NTOK*HD];
__device__ float g_v  [NTOK*HD];
__device__ float g_s  [64u*1024u*1024u];      // [B*H][T][T] scores/probs (256MB)
__device__ float g_att[NTOK*CDIM];
__device__ float g_h  [NTOK*CDIM];
__device__ float g_hn [NTOK*CDIM];
__device__ int   g_top [NTOK*TOPK];
__device__ float g_topw[NTOK*TOPK];
__device__ int   g_tok_of_slot[MAXSLOT];
__device__ float g_w_of_slot  [MAXSLOT];
__device__ int   g_slot_of_tok[NTOK*TOPK];
__device__ int   g_off_pad[NEXP];
__device__ int   g_cnt_pad[NEXP];
__device__ float g_hid [MAXSLOT*FDIM];
__device__ float g_ctb [MAXSLOT*CDIM];
__device__ float g_shid[NTOK*FSH];
__device__ float g_sout[NTOK*CDIM];

// ---------------- helpers ----------------
__device__ __forceinline__ float siluf(float x) { return x / (1.0f + expf(-x)); }

__device__ __forceinline__ float block_reduce_sum256(float v) {
    __shared__ float sm[8];
    __syncthreads();
    int lane = threadIdx.x & 31, w = threadIdx.x >> 5;
    #pragma unroll
    for (int o = 16; o; o >>= 1) v += __shfl_xor_sync(0xffffffffu, v, o);
    if (lane == 0) sm[w] = v;
    __syncthreads();
    float r = (threadIdx.x < (blockDim.x >> 5)) ? sm[threadIdx.x] : 0.0f;
    if (w == 0) {
        #pragma unroll
        for (int o = 4; o; o >>= 1) r += __shfl_xor_sync(0xffffffffu, r, o);
        if (lane == 0) sm[0] = r;
    }
    __syncthreads();
    return sm[0];
}

__device__ __forceinline__ float block_reduce_max256(float v) {
    __shared__ float sm[8];
    __syncthreads();
    int lane = threadIdx.x & 31, w = threadIdx.x >> 5;
    #pragma unroll
    for (int o = 16; o; o >>= 1) v = fmaxf(v, __shfl_xor_sync(0xffffffffu, v, o));
    if (lane == 0) sm[w] = v;
    __syncthreads();
    float r = (threadIdx.x < (blockDim.x >> 5)) ? sm[threadIdx.x] : -INFINITY;
    if (w == 0) {
        #pragma unroll
        for (int o = 4; o; o >>= 1) r = fmaxf(r, __shfl_xor_sync(0xffffffffu, r, o));
        if (lane == 0) sm[0] = r;
    }
    __syncthreads();
    return sm[0];
}

// ---------------- generic 64x64 GEMM core (BK=16, 256 threads, 4x4 microtile) --
template<int DUAL>
__device__ __forceinline__ void gemm_core(
    const float* __restrict__ A, int lda, const int* __restrict__ ridx, int m0,
    const float* __restrict__ B1, const float* __restrict__ B3, int ldb, int n0,
    int K, float (&acc1)[4][4], float (&acc3)[4][4])
{
    __shared__ float sA [64*16];
    __shared__ float sB1[16*64];
    __shared__ float sB3[DUAL ? 16*64 : 4];
    const int tid = threadIdx.x;
    const int tx = tid & 15, ty = tid >> 4;
    const int am = tid >> 2, ak = tid & 3;    // A: row am, 4-float chunk ak
    const int bk = tid >> 4, bn = tid & 15;   // B: k-row bk, 4-float col chunk bn
    const int arow = ridx ? ridx[m0 + am] : (m0 + am);
    const float* Aptr  = A  + (size_t)arow * lda + ak * 4;
    const float* B1ptr = B1 + (size_t)bk * ldb + n0 + bn * 4;
    const float* B3ptr = DUAL ? (B3 + (size_t)bk * ldb + n0 + bn * 4) : B1;
    float4* sA4  = (float4*)sA;
    float4* sB14 = (float4*)sB1;
    float4* sB34 = (float4*)sB3;

    for (int k0 = 0; k0 < K; k0 += 16) {
        __syncthreads();
        sA4 [am*4  + ak] = *(const float4*)(Aptr  + k0);
        sB14[bk*16 + bn] = *(const float4*)(B1ptr + (size_t)k0 * ldb);
        if (DUAL) sB34[bk*16 + bn] = *(const float4*)(B3ptr + (size_t)k0 * ldb);
        __syncthreads();
        #pragma unroll
        for (int k = 0; k < 16; k++) {
            float4 b1 = sB14[k*16 + tx];
            float4 b3;
            if (DUAL) b3 = sB34[k*16 + tx];
            #pragma unroll
            for (int i = 0; i < 4; i++) {
                float a = sA[(ty*4 + i)*16 + k];
                acc1[i][0] += a*b1.x; acc1[i][1] += a*b1.y;
                acc1[i][2] += a*b1.z; acc1[i][3] += a*b1.w;
                if (DUAL) {
                    acc3[i][0] += a*b3.x; acc3[i][1] += a*b3.y;
                    acc3[i][2] += a*b3.z; acc3[i][3] += a*b3.w;
                }
            }
        }
    }
}

// ---------------- kernels ----------------
__global__ __launch_bounds__(256)
void k_rmsnorm(const float* __restrict__ X, const float* __restrict__ G,
               float* __restrict__ O)
{
    int n = blockIdx.x;
    const float4* x4 = (const float4*)(X + (size_t)n * CDIM);
    const float4* g4 = (const float4*)G;
    float4 v = x4[threadIdx.x];
    float ss = v.x*v.x + v.y*v.y + v.z*v.z + v.w*v.w;
    float tot = block_reduce_sum256(ss);
    float r = 1.0f / sqrtf(tot * (1.0f / CDIM) + 1e-6f);
    float4 g = g4[threadIdx.x];
    float4 o = make_float4(v.x*r*g.x, v.y*r*g.y, v.z*r*g.z, v.w*r*g.w);
    ((float4*)(O + (size_t)n * CDIM))[threadIdx.x] = o;
}

template<bool RESID>
__global__ __launch_bounds__(256)
void k_gemm_plain(const float* __restrict__ A, int lda,
                  const float* __restrict__ B, int ldb,
                  float* __restrict__ C, int ldc,
                  const float* __restrict__ D, int K)
{
    int n0 = blockIdx.x * 64, m0 = blockIdx.y * 64;
    float acc[4][4] = {}; float d3[4][4];
    gemm_core<0>(A, lda, nullptr, m0, B, nullptr, ldb, n0, K, acc, d3);
    int tx = threadIdx.x & 15, ty = threadIdx.x >> 4;
    #pragma unroll
    for (int i = 0; i < 4; i++) {
        int r = m0 + ty*4 + i;
        float4 v = make_float4(acc[i][0], acc[i][1], acc[i][2], acc[i][3]);
        if (RESID) {
            float4 dv = *(const float4*)(D + (size_t)r * ldc + n0 + tx*4);
            v.x += dv.x; v.y += dv.y; v.z += dv.z; v.w += dv.w;
        }
        *(float4*)(C + (size_t)r * ldc + n0 + tx*4) = v;
    }
}

template<bool EXPERT>
__global__ __launch_bounds__(256)
void k_gemm_dualsilu(const float* __restrict__ A, int lda,
                     const float* __restrict__ B1b, const float* __restrict__ B3b, int ldb,
                     float* __restrict__ C, int ldc, int K, int M, size_t bstride)
{
    int e = blockIdx.z;
    int m0 = blockIdx.y * 64;
    const int* ridx; float* Cb;
    if (EXPERT) {
        if (m0 >= g_cnt_pad[e]) return;
        int off = g_off_pad[e];
        ridx = g_tok_of_slot + off;
        Cb = C + (size_t)off * ldc;
    } else {
        if (m0 >= M) return;
        ridx = nullptr; Cb = C;
    }
    const float* B1 = B1b + (size_t)e * bstride;
    const float* B3 = B3b + (size_t)e * bstride;
    int n0 = blockIdx.x * 64;
    float acc1[4][4] = {}, acc3[4][4] = {};
    gemm_core<1>(A, lda, ridx, m0, B1, B3, ldb, n0, K, acc1, acc3);
    int tx = threadIdx.x & 15, ty = threadIdx.x >> 4;
    #pragma unroll
    for (int i = 0; i < 4; i++) {
        int r = m0 + ty*4 + i;
        float4 v;
        v.x = acc1[i][0] * siluf(acc3[i][0]);
        v.y = acc1[i][1] * siluf(acc3[i][1]);
        v.z = acc1[i][2] * siluf(acc3[i][2]);
        v.w = acc1[i][3] * siluf(acc3[i][3]);
        *(float4*)(Cb + (size_t)r * ldc + n0 + tx*4) = v;
    }
}

__global__ __launch_bounds__(256)
void k_expert_down(const float* __restrict__ HID, const float* __restrict__ W2b,
                   float* __restrict__ CT)
{
    int e = blockIdx.z;
    int m0 = blockIdx.y * 64;
    if (m0 >= g_cnt_pad[e]) return;
    int off = g_off_pad[e];
    const float* A = HID + (size_t)off * FDIM;
    const float* B = W2b + (size_t)e * FDIM * CDIM;
    int n0 = blockIdx.x * 64;
    float acc[4][4] = {}; float d3[4][4];
    gemm_core<0>(A, FDIM, nullptr, m0, B, nullptr, CDIM, n0, FDIM, acc, d3);
    int tx = threadIdx.x & 15, ty = threadIdx.x >> 4;
    #pragma unroll
    for (int i = 0; i < 4; i++) {
        int r = m0 + ty*4 + i;
        float w = g_w_of_slot[off + r];
        float4 v = make_float4(acc[i][0]*w, acc[i][1]*w, acc[i][2]*w, acc[i][3]*w);
        *(float4*)(CT + (size_t)(off + r) * CDIM + n0 + tx*4) = v;
    }
}

// scores: S[bh][t][s] = (Q_bh @ K_b^T) / 8, causal tiles only
__global__ __launch_bounds__(256)
void k_scores(const float* __restrict__ Q, const float* __restrict__ Kb,
              float* __restrict__ S)
{
    int kt = blockIdx.x, qt = blockIdx.y, bh = blockIdx.z;
    if (kt > qt) return;
    int b = bh >> 4, h = bh & 15;
    __shared__ float sQ [64*64];
    __shared__ float sKt[64*64];
    int tid = threadIdx.x;
    const float4* Q4 = (const float4*)(Q + (size_t)(b*1024 + qt*64) * CDIM + h*HD);
    #pragma unroll
    for (int it = 0; it < 4; it++) {
        int idx = tid + it*256;
        int t = idx >> 4, f4 = idx & 15;
        ((float4*)sQ)[t*16 + f4] = Q4[t*256 + f4];
    }
    const float4* K4 = (const float4*)(Kb + (size_t)(b*1024 + kt*64) * HD);
    #pragma unroll
    for (int it = 0; it < 4; it++) {
        int idx = tid + it*256;
        int f4 = idx >> 6, s = idx & 63;
        float4 v = K4[s*16 + f4];
        sKt[(f4*4 + 0)*64 + s] = v.x;
        sKt[(f4*4 + 1)*64 + s] = v.y;
        sKt[(f4*4 + 2)*64 + s] = v.z;
        sKt[(f4*4 + 3)*64 + s] = v.w;
    }
    __syncthreads();
    int tx = tid & 15, ty = tid >> 4;
    float acc[4][4] = {};
    #pragma unroll 16
    for (int d = 0; d < 64; d++) {
        float4 bv = ((float4*)sKt)[d*16 + tx];
        #pragma unroll
        for (int i = 0; i < 4; i++) {
            float a = sQ[(ty*4 + i)*64 + d];
            acc[i][0] += a*bv.x; acc[i][1] += a*bv.y;
            acc[i][2] += a*bv.z; acc[i][3] += a*bv.w;
        }
    }
    float* Sout = S + (size_t)bh*1024*1024 + (size_t)(qt*64)*1024 + kt*64;
    #pragma unroll
    for (int i = 0; i < 4; i++) {
        float4 v = make_float4(acc[i][0]*0.125f, acc[i][1]*0.125f,
                               acc[i][2]*0.125f, acc[i][3]*0.125f);
        ((float4*)(Sout + (size_t)(ty*4 + i)*1024))[tx] = v;
    }
}

__global__ __launch_bounds__(256)
void k_softmax(float* __restrict__ S)
{
    int t = blockIdx.x, bh = blockIdx.y;
    float* row = S + (size_t)bh*1024*1024 + (size_t)t*1024;
    int L = t + 1;
    int Lw = ((t >> 6) + 1) << 6;
    int tid = threadIdx.x;
    float mx = -INFINITY;
    for (int s = tid; s < L; s += 256) mx = fmaxf(mx, row[s]);
    mx = block_reduce_max256(mx);
    float ev[4]; float sum = 0.0f;
    #pragma unroll
    for (int it = 0; it < 4; it++) {
        int s = tid + it*256;
        ev[it] = 0.0f;
        if (s < L) { ev[it] = expf(row[s] - mx); sum += ev[it]; }
    }
    float tot = block_reduce_sum256(sum);
    float inv = 1.0f / tot;
    #pragma unroll
    for (int it = 0; it < 4; it++) {
        int s = tid + it*256;
        if (s < Lw) row[s] = ev[it] * inv;
    }
}

__global__ __launch_bounds__(256)
void k_pv(const float* __restrict__ P, const float* __restrict__ V,
          float* __restrict__ O)
{
    int qt = blockIdx.x, bh = blockIdx.y;
    int b = bh >> 4, h = bh & 15;
    const float* A = P + (size_t)bh * 1024 * 1024;
    const float* B = V + (size_t)b * 1024 * HD;
    int K = (qt + 1) * 64;
    float acc[4][4] = {}; float d3[4][4];
    gemm_core<0>(A, 1024, nullptr, qt*64, B, nullptr, HD, 0, K, acc, d3);
    int tx = threadIdx.x & 15, ty = threadIdx.x >> 4;
    #pragma unroll
    for (int i = 0; i < 4; i++) {
        int r = qt*64 + ty*4 + i;
        float4 v = make_float4(acc[i][0], acc[i][1], acc[i][2], acc[i][3]);
        *(float4*)(O + (size_t)(b*1024 + r) * CDIM + h*HD + tx*4) = v;
    }
}

__global__ __launch_bounds__(128)
void k_router(const float* __restrict__ HN, const float* __restrict__ WR,
              const float* __restrict__ RB)
{
    int n = blockIdx.x * 4 + (threadIdx.x >> 5);
    int lane = threadIdx.x & 31;
    const float* x = HN + (size_t)n * CDIM;
    float p[NEXP] = {};
    for (int c = lane; c < CDIM; c += 32) {
        float xv = x[c];
        #pragma unroll
        for (int e = 0; e < NEXP; e++) p[e] += xv * WR[c*NEXP + e];
    }
    #pragma unroll
    for (int e = 0; e < NEXP; e++) {
        #pragma unroll
        for (int o = 16; o; o >>= 1)
            p[e] += __shfl_xor_sync(0xffffffffu, p[e], o);
    }
    if (lane == 0) {
        float logit[NEXP], biased[NEXP];
        #pragma unroll
        for (int e = 0; e < NEXP; e++) {
            logit[e]  = p[e] * 0.03125f;   // 1/sqrt(1024)
            biased[e] = logit[e] + RB[e];
        }
        int i0 = 0;
        #pragma unroll
        for (int e = 1; e < NEXP; e++) if (biased[e] > biased[i0]) i0 = e;
        int i1 = (i0 == 0) ? 1 : 0;
        #pragma unroll
        for (int e = 0; e < NEXP; e++)
            if (e != i0 && e != i1 && biased[e] > biased[i1]) i1 = e;
        // fix order for the i1 seed (must be best among e != i0 with lowest-index tie-break)
        // re-scan cleanly:
        int j1 = -1;
        #pragma unroll
        for (int e = 0; e < NEXP; e++) {
            if (e == i0) continue;
            if (j1 < 0 || biased[e] > biased[j1]) j1 = e;
        }
        i1 = j1;
        float m  = fmaxf(logit[i0], logit[i1]);
        float e0 = expf(logit[i0] - m), e1 = expf(logit[i1] - m);
        float inv = 1.0f / (e0 + e1);
        g_top [n*2]     = i0; g_top [n*2 + 1] = i1;
        g_topw[n*2]     = e0 * inv;
        g_topw[n*2 + 1] = e1 * inv;
    }
}

__global__ __launch_bounds__(256)
void k_place()
{
    __shared__ int cnt[NEXP], offp[NEXP], cntp[NEXP], cur[NEXP];
    int tid = threadIdx.x;
    if (tid < NEXP) cnt[tid] = 0;
    __syncthreads();
    for (int i = tid; i < NTOK*TOPK; i += 256) atomicAdd(&cnt[g_top[i]], 1);
    __syncthreads();
    if (tid == 0) {
        int o = 0;
        for (int e = 0; e < NEXP; e++) {
            offp[e] = o;
            cntp[e] = ((cnt[e] + 63) >> 6) << 6;
            cur[e]  = o;
            g_off_pad[e] = o;
            g_cnt_pad[e] = cntp[e];
            o += cntp[e];
        }
    }
    __syncthreads();
    for (int i = tid; i < NTOK*TOPK; i += 256) {
        int e = g_top[i];
        int s = atomicAdd(&cur[e], 1);
        g_tok_of_slot[s] = i >> 1;
        g_w_of_slot[s]   = g_topw[i];
        g_slot_of_tok[i] = s;
    }
    __syncthreads();
    for (int e = 0; e < NEXP; e++) {
        int start = offp[e] + cnt[e];
        int end   = offp[e] + cntp[e];
        for (int i = start + tid; i < end; i += 256) {
            g_tok_of_slot[i] = 0;
            g_w_of_slot[i]   = 0.0f;
        }
    }
}

__global__ __launch_bounds__(256)
void k_combine(const float* __restrict__ SOUT, const float* __restrict__ CT,
               float* __restrict__ OUT)
{
    int n = blockIdx.x;
    int s0 = g_slot_of_tok[n*2], s1 = g_slot_of_tok[n*2 + 1];
    const float4* a  = (const float4*)(SOUT + (size_t)n  * CDIM);
    const float4* c0 = (const float4*)(CT   + (size_t)s0 * CDIM);
    const float4* c1 = (const float4*)(CT   + (size_t)s1 * CDIM);
    float4* o = (float4*)(OUT + (size_t)n * CDIM);
    int i = threadIdx.x;
    float4 va = a[i], v0 = c0[i], v1 = c1[i];
    o[i] = make_float4(va.x + v0.x + v1.x, va.y + v0.y + v1.y,
                       va.z + v0.z + v1.z, va.w + v0.w + v1.w);
}

// ---------------- launch ----------------
extern "C" void kernel_launch(void* const* d_in, const int* in_sizes, int n_in,
                              void* d_out, int out_size)
{
    const float* x     = (const float*)d_in[0];
    const float* ga    = (const float*)d_in[1];
    const float* wq    = (const float*)d_in[2];
    const float* wkvd  = (const float*)d_in[3];
    const float* wku   = (const float*)d_in[4];
    const float* wvu   = (const float*)d_in[5];
    const float* wo    = (const float*)d_in[6];
    const float* gm    = (const float*)d_in[7];
    const float* wr    = (const float*)d_in[8];
    const float* rb    = (const float*)d_in[9];
    const float* ew1   = (const float*)d_in[10];
    const float* ew2   = (const float*)d_in[11];
    const float* ew3   = (const float*)d_in[12];
    const float* sw1   = (const float*)d_in[13];
    const float* sw2   = (const float*)d_in[14];
    const float* sw3   = (const float*)d_in[15];
    float* out = (float*)d_out;

    float *xn, *q, *kv, *kb, *vb, *sb, *att, *hb, *hn, *hid, *ctb, *shid, *sout;
    cudaGetSymbolAddress((void**)&xn,   g_xn);
    cudaGetSymbolAddress((void**)&q,    g_q);
    cudaGetSymbolAddress((void**)&kv,   g_kv);
    cudaGetSymbolAddress((void**)&kb,   g_k);
    cudaGetSymbolAddress((void**)&vb,   g_v);
    cudaGetSymbolAddress((void**)&sb,   g_s);
    cudaGetSymbolAddress((void**)&att,  g_att);
    cudaGetSymbolAddress((void**)&hb,   g_h);
    cudaGetSymbolAddress((void**)&hn,   g_hn);
    cudaGetSymbolAddress((void**)&hid,  g_hid);
    cudaGetSymbolAddress((void**)&ctb,  g_ctb);
    cudaGetSymbolAddress((void**)&shid, g_shid);
    cudaGetSymbolAddress((void**)&sout, g_sout);

    // ---- attention ----
    k_rmsnorm<<<NTOK, 256>>>(x, ga, xn);
    k_gemm_plain<false><<<dim3(CDIM/64, NTOK/64), 256>>>(xn, CDIM, wq,   CDIM, q,  CDIM, nullptr, CDIM);
    k_gemm_plain<false><<<dim3(LAT/64,  NTOK/64), 256>>>(xn, CDIM, wkvd, LAT,  kv, LAT,  nullptr, CDIM);
    k_gemm_plain<false><<<dim3(1,       NTOK/64), 256>>>(kv, LAT,  wku,  HD,   kb, HD,   nullptr, LAT);
    k_gemm_plain<false><<<dim3(1,       NTOK/64), 256>>>(kv, LAT,  wvu,  HD,   vb, HD,   nullptr, LAT);
    k_scores <<<dim3(16, 16, 64), 256>>>(q, kb, sb);
    k_softmax<<<dim3(1024, 64),   256>>>(sb);
    k_pv     <<<dim3(16, 64),     256>>>(sb, vb, att);
    k_gemm_plain<true><<<dim3(CDIM/64, NTOK/64), 256>>>(att, CDIM, wo, CDIM, hb, CDIM, x, CDIM);

    // ---- MoE ----
    k_rmsnorm<<<NTOK, 256>>>(hb, gm, hn);
    k_router<<<NTOK/4, 128>>>(hn, wr, rb);
    k_place<<<1, 256>>>();
    k_gemm_dualsilu<true><<<dim3(FDIM/64, 64, NEXP), 256>>>(
        hn, CDIM, ew1, ew3, FDIM, hid, FDIM, CDIM, 0, (size_t)CDIM * FDIM);
    k_expert_down<<<dim3(CDIM/64, 64, NEXP), 256>>>(hid, ew2, ctb);
    k_gemm_dualsilu<false><<<dim3(FSH/64, NTOK/64, 1), 256>>>(
        hn, CDIM, sw1, sw3, FSH, shid, FSH, CDIM, NTOK, 0);
    k_gemm_plain<true><<<dim3(CDIM/64, NTOK/64), 256>>>(shid, FSH, sw2, CDIM, sout, CDIM, hb, FSH);
    k_combine<<<NTOK, 256>>>(sout, ctb, out);
}

// round 2
// speedup vs baseline: 2.3136x; 2.3136x over previous
#include <cuda_runtime.h>
#include <math.h>

// ---------------- problem dims ----------------
#define NTOK 4096
#define CDIM 1024
#define HD 64
#define LAT 512
#define NEXP 8
#define FDIM 1024
#define FSH 2048
#define MAXSLOT 9216

// ---------------- scratch ----------------
__device__ float g_xn [NTOK*CDIM];
__device__ float g_q  [NTOK*CDIM];
__device__ float g_kv [NTOK*LAT];
__device__ float g_k  [NTOK*HD];
__device__ float g_v  [NTOK*HD];
__device__ float g_s  [64u*1024u*1024u];
__device__ float g_att[NTOK*CDIM];
__device__ float g_h  [NTOK*CDIM];
__device__ float g_hn [NTOK*CDIM];
__device__ int   g_top[NTOK*2];
__device__ float g_topw[NTOK*2];
__device__ int   g_tok_of_slot[MAXSLOT];
__device__ float g_w_of_slot[MAXSLOT];
__device__ int   g_slot_of_tok[NTOK*2];
__device__ int   g_off_pad[NEXP];
__device__ int   g_cnt_pad[NEXP];
__device__ float g_hid1[MAXSLOT*FDIM];
__device__ float g_hid3[MAXSLOT*FDIM];
__device__ float g_hid [MAXSLOT*FDIM];
__device__ float g_ctb [MAXSLOT*CDIM];
__device__ float g_sh1 [NTOK*FSH];
__device__ float g_sh3 [NTOK*FSH];
__device__ float g_shid[NTOK*FSH];
__device__ float g_sout[NTOK*CDIM];

// ---------------- helpers ----------------
__device__ __forceinline__ float siluf(float x) { return x / (1.0f + expf(-x)); }

__device__ __forceinline__ unsigned f2tf(float f) {
    unsigned u; asm("cvt.rna.tf32.f32 %0, %1;" : "=r"(u) : "f"(f)); return u;
}

#define MMA_TF32(d, a, b) asm volatile( \
  "mma.sync.aligned.m16n8k8.row.col.f32.tf32.tf32.f32 " \
  "{%0,%1,%2,%3}, {%4,%5,%6,%7}, {%8,%9}, {%0,%1,%2,%3};" \
  : "+f"(d[0]), "+f"(d[1]), "+f"(d[2]), "+f"(d[3]) \
  : "r"(a[0]), "r"(a[1]), "r"(a[2]), "r"(a[3]), "r"(b[0]), "r"(b[1]))

__device__ __forceinline__ float block_reduce_sum256(float v) {
    __shared__ float sm[8];
    __syncthreads();
    int lane = threadIdx.x & 31, w = threadIdx.x >> 5;
    #pragma unroll
    for (int o = 16; o; o >>= 1) v += __shfl_xor_sync(0xffffffffu, v, o);
    if (lane == 0) sm[w] = v;
    __syncthreads();
    float r = (threadIdx.x < 8) ? sm[threadIdx.x] : 0.0f;
    if (w == 0) {
        #pragma unroll
        for (int o = 4; o; o >>= 1) r += __shfl_xor_sync(0xffffffffu, r, o);
        if (lane == 0) sm[0] = r;
    }
    __syncthreads();
    return sm[0];
}

__device__ __forceinline__ float block_reduce_max256(float v) {
    __shared__ float sm[8];
    __syncthreads();
    int lane = threadIdx.x & 31, w = threadIdx.x >> 5;
    #pragma unroll
    for (int o = 16; o; o >>= 1) v = fmaxf(v, __shfl_xor_sync(0xffffffffu, v, o));
    if (lane == 0) sm[w] = v;
    __syncthreads();
    float r = (threadIdx.x < 8) ? sm[threadIdx.x] : -INFINITY;
    if (w == 0) {
        #pragma unroll
        for (int o = 4; o; o >>= 1) r = fmaxf(r, __shfl_xor_sync(0xffffffffu, r, o));
        if (lane == 0) sm[0] = r;
    }
    __syncthreads();
    return sm[0];
}

// ---------------- tensor-core TF32 GEMM ----------------
enum { M_PLAIN = 0, M_RESID, M_KVUP, M_SCORES, M_PV, M_EXPUP, M_EXPDOWN };

template<int MODE, int BN>
__global__ __launch_bounds__(256)
void gemm_tc(const float* __restrict__ Aa, int lda,
             const float* __restrict__ Ba, int ldb,
             const float* __restrict__ B2a,
             float* __restrict__ Ca, int ldc,
             const float* __restrict__ Da, int K)
{
    constexpr int SAS = 20;        // BK(16) + 4 pad
    constexpr int SBS = BN + 8;
    constexpr int NT  = BN / 16;   // n8 tiles per warp (2 n-warps)
    constexpr int NCH = BN / 4;    // float4 chunks per B row
    constexpr int TB  = (BN * 4) / 256;  // B f4 chunks per thread (2 or 1)
    __shared__ unsigned sA[2][128 * SAS];
    __shared__ unsigned sB[2][16 * SBS];

    const int tid = threadIdx.x;
    const int nb = blockIdx.x, mb = blockIdx.y, z = blockIdx.z;
    const int m0 = mb * 128, n0 = nb * BN;

    const float* A = Aa; const float* B = Ba; float* C = Ca; const float* D = Da;
    const int* ridx = nullptr;
    const float* wrow = nullptr;

    if (MODE == M_SCORES) {
        if (nb > mb) return;
        int b = z >> 4, h = z & 15;
        A = g_q + (size_t)(b * 1024) * 1024 + h * 64;  lda = 1024;
        B = g_k + (size_t)b * 1024 * 64;
        C = g_s + (size_t)z * 1024 * 1024;             ldc = 1024;
        K = 64;
    } else if (MODE == M_PV) {
        int b = z >> 4, h = z & 15;
        A = g_s + (size_t)z * 1024 * 1024;             lda = 1024;
        B = g_v + (size_t)b * 1024 * 64;               ldb = 64;
        C = g_att + (size_t)(b * 1024) * 1024 + h * 64; ldc = 1024;
        K = (mb + 1) * 128;
    } else if (MODE == M_EXPUP) {
        if (m0 >= g_cnt_pad[z]) return;
        int off = g_off_pad[z];
        ridx = g_tok_of_slot + off;
        A = g_hn; lda = CDIM;
        B = Ba + (size_t)z * CDIM * FDIM;
        C = Ca + (size_t)off * FDIM;
    } else if (MODE == M_EXPDOWN) {
        if (m0 >= g_cnt_pad[z]) return;
        int off = g_off_pad[z];
        A = g_hid + (size_t)off * FDIM; lda = FDIM;
        B = Ba + (size_t)z * FDIM * CDIM;
        C = g_ctb + (size_t)off * CDIM; ldc = CDIM;
        wrow = g_w_of_slot + off;
    }

    const int lane = tid & 31, warp = tid >> 5;
    const int wm = warp & 3, wn = warp >> 2;
    const int mw = wm * 32, nw = wn * (BN / 2);
    const int grp = lane >> 2, tig = lane & 3;

    float acc[2][NT][4];
    #pragma unroll
    for (int i = 0; i < 2; i++)
        #pragma unroll
        for (int j = 0; j < NT; j++)
            #pragma unroll
            for (int r = 0; r < 4; r++) acc[i][j][r] = 0.0f;

    auto LDGA = [&](float4 (&r)[2], int k0) {
        #pragma unroll
        for (int t = 0; t < 2; t++) {
            int c = tid + 256 * t;
            int row = c >> 2, kc = c & 3;
            int gr = (MODE == M_EXPUP) ? ridx[m0 + row] : (m0 + row);
            r[t] = *(const float4*)(A + (size_t)gr * lda + k0 + kc * 4);
        }
    };
    auto STSA = [&](const float4 (&r)[2], int s) {
        #pragma unroll
        for (int t = 0; t < 2; t++) {
            int c = tid + 256 * t;
            int row = c >> 2, kc = c & 3;
            uint4 u = make_uint4(f2tf(r[t].x), f2tf(r[t].y), f2tf(r[t].z), f2tf(r[t].w));
            *(uint4*)&sA[s][row * SAS + kc * 4] = u;
        }
    };
    auto LDGB = [&](float4 (&r)[TB], int k0) {
        #pragma unroll
        for (int t = 0; t < TB; t++) {
            int c = tid + 256 * t;
            if (MODE == M_SCORES) {
                int sx = c >> 2, dc = c & 3;
                r[t] = *(const float4*)(B + (size_t)(n0 + sx) * 64 + k0 + dc * 4);
            } else if (MODE == M_KVUP) {
                int krow = c / NCH, nc = c % NCH;
                const float* base = (nc < 16) ? B : B2a;
                r[t] = *(const float4*)(base + (size_t)(k0 + krow) * 64 + (nc & 15) * 4);
            } else {
                int krow = c / NCH, nc = c % NCH;
                r[t] = *(const float4*)(B + (size_t)(k0 + krow) * ldb + n0 + nc * 4);
            }
        }
    };
    auto STSB = [&](const float4 (&r)[TB], int s) {
        #pragma unroll
        for (int t = 0; t < TB; t++) {
            int c = tid + 256 * t;
            if (MODE == M_SCORES) {
                int sx = c >> 2, dc = c & 3;
                sB[s][(dc * 4 + 0) * SBS + sx] = f2tf(r[t].x);
                sB[s][(dc * 4 + 1) * SBS + sx] = f2tf(r[t].y);
                sB[s][(dc * 4 + 2) * SBS + sx] = f2tf(r[t].z);
                sB[s][(dc * 4 + 3) * SBS + sx] = f2tf(r[t].w);
            } else {
                int krow = c / NCH, nc = c % NCH;
                uint4 u = make_uint4(f2tf(r[t].x), f2tf(r[t].y), f2tf(r[t].z), f2tf(r[t].w));
                *(uint4*)&sB[s][krow * SBS + nc * 4] = u;
            }
        }
    };
    auto COMP = [&](int s) {
        #pragma unroll
        for (int k8 = 0; k8 < 16; k8 += 8) {
            unsigned bF[NT][2], aF[2][4];
            #pragma unroll
            for (int j = 0; j < NT; j++) {
                int n = nw + j * 8 + grp;
                bF[j][0] = sB[s][(k8 + tig) * SBS + n];
                bF[j][1] = sB[s][(k8 + 4 + tig) * SBS + n];
            }
            #pragma unroll
            for (int i = 0; i < 2; i++) {
                int m = mw + i * 16 + grp;
                aF[i][0] = sA[s][m * SAS + k8 + tig];
                aF[i][1] = sA[s][(m + 8) * SAS + k8 + tig];
                aF[i][2] = sA[s][m * SAS + k8 + 4 + tig];
                aF[i][3] = sA[s][(m + 8) * SAS + k8 + 4 + tig];
            }
            #pragma unroll
            for (int i = 0; i < 2; i++)
                #pragma unroll
                for (int j = 0; j < NT; j++)
                    MMA_TF32(acc[i][j], aF[i], bF[j]);
        }
    };

    const int KT = K >> 4;
    float4 ra[2]; float4 rb[TB];
    LDGA(ra, 0); LDGB(rb, 0);
    STSA(ra, 0); STSB(rb, 0);
    __syncthreads();
    for (int kt = 0; kt < KT; kt++) {
        int cur = kt & 1;
        bool more = (kt + 1 < KT);
        if (more) { LDGA(ra, (kt + 1) * 16); LDGB(rb, (kt + 1) * 16); }
        COMP(cur);
        __syncthreads();
        if (more) { STSA(ra, cur ^ 1); STSB(rb, cur ^ 1); __syncthreads(); }
    }

    // epilogue
    #pragma unroll
    for (int i = 0; i < 2; i++) {
        #pragma unroll
        for (int j = 0; j < NT; j++) {
            #pragma unroll
            for (int half = 0; half < 2; half++) {
                int ml = mw + i * 16 + grp + half * 8;
                int nl = nw + j * 8 + 2 * tig;
                float v0 = acc[i][j][half * 2 + 0];
                float v1 = acc[i][j][half * 2 + 1];
                int gm = m0 + ml, gn = n0 + nl;
                if (MODE == M_SCORES) {
                    *(float2*)(C + (size_t)gm * 1024 + gn) = make_float2(v0 * 0.125f, v1 * 0.125f);
                } else if (MODE == M_KVUP) {
                    if (nl < 64) *(float2*)(g_k + (size_t)gm * 64 + nl) = make_float2(v0, v1);
                    else         *(float2*)(g_v + (size_t)gm * 64 + nl - 64) = make_float2(v0, v1);
                } else if (MODE == M_EXPDOWN) {
                    float w = wrow[gm];
                    *(float2*)(C + (size_t)gm * ldc + gn) = make_float2(v0 * w, v1 * w);
                } else if (MODE == M_RESID) {
                    float2 d = *(const float2*)(D + (size_t)gm * ldc + gn);
                    *(float2*)(C + (size_t)gm * ldc + gn) = make_float2(v0 + d.x, v1 + d.y);
                } else {  // PLAIN, PV, EXPUP
                    *(float2*)(C + (size_t)gm * ldc + gn) = make_float2(v0, v1);
                }
            }
        }
    }
}

// ---------------- elementwise / small kernels ----------------
__global__ __launch_bounds__(256)
void k_rmsnorm(const float* __restrict__ X, const float* __restrict__ G,
               float* __restrict__ O)
{
    int n = blockIdx.x;
    const float4* x4 = (const float4*)(X + (size_t)n * CDIM);
    const float4* g4 = (const float4*)G;
    float4 v = x4[threadIdx.x];
    float ss = v.x*v.x + v.y*v.y + v.z*v.z + v.w*v.w;
    float tot = block_reduce_sum256(ss);
    float r = 1.0f / sqrtf(tot * (1.0f / CDIM) + 1e-6f);
    float4 g = g4[threadIdx.x];
    ((float4*)(O + (size_t)n * CDIM))[threadIdx.x] =
        make_float4(v.x*r*g.x, v.y*r*g.y, v.z*r*g.z, v.w*r*g.w);
}

__global__ __launch_bounds__(256)
void k_softmax(float* __restrict__ S)
{
    int t = blockIdx.x, bh = blockIdx.y;
    float* row = S + (size_t)bh * 1024 * 1024 + (size_t)t * 1024;
    int L = t + 1;
    int Lw = ((t >> 7) + 1) << 7;    // pad to 128 multiple
    int tid = threadIdx.x;
    float mx = -INFINITY;
    for (int s = tid; s < L; s += 256) mx = fmaxf(mx, row[s]);
    mx = block_reduce_max256(mx);
    float ev[4]; float sum = 0.0f;
    #pragma unroll
    for (int it = 0; it < 4; it++) {
        int s = tid + it * 256;
        ev[it] = 0.0f;
        if (s < L) { ev[it] = expf(row[s] - mx); sum += ev[it]; }
    }
    float tot = block_reduce_sum256(sum);
    float inv = 1.0f / tot;
    #pragma unroll
    for (int it = 0; it < 4; it++) {
        int s = tid + it * 256;
        if (s < Lw) row[s] = ev[it] * inv;
    }
}

__global__ __launch_bounds__(128)
void k_router(const float* __restrict__ HN, const float* __restrict__ WR,
              const float* __restrict__ RB)
{
    int n = blockIdx.x * 4 + (threadIdx.x >> 5);
    int lane = threadIdx.x & 31;
    const float* x = HN + (size_t)n * CDIM;
    float p[NEXP] = {};
    for (int c = lane; c < CDIM; c += 32) {
        float xv = x[c];
        #pragma unroll
        for (int e = 0; e < NEXP; e++) p[e] += xv * WR[c * NEXP + e];
    }
    #pragma unroll
    for (int e = 0; e < NEXP; e++) {
        #pragma unroll
        for (int o = 16; o; o >>= 1)
            p[e] += __shfl_xor_sync(0xffffffffu, p[e], o);
    }
    if (lane == 0) {
        float logit[NEXP], biased[NEXP];
        #pragma unroll
        for (int e = 0; e < NEXP; e++) {
            logit[e]  = p[e] * 0.03125f;
            biased[e] = logit[e] + RB[e];
        }
        int i0 = 0;
        #pragma unroll
        for (int e = 1; e < NEXP; e++) if (biased[e] > biased[i0]) i0 = e;
        int i1 = -1;
        #pragma unroll
        for (int e = 0; e < NEXP; e++) {
            if (e == i0) continue;
            if (i1 < 0 || biased[e] > biased[i1]) i1 = e;
        }
        float m  = fmaxf(logit[i0], logit[i1]);
        float e0 = expf(logit[i0] - m), e1 = expf(logit[i1] - m);
        float inv = 1.0f / (e0 + e1);
        g_top [n*2]     = i0; g_top [n*2 + 1] = i1;
        g_topw[n*2]     = e0 * inv;
        g_topw[n*2 + 1] = e1 * inv;
    }
}

__global__ __launch_bounds__(256)
void k_place()
{
    __shared__ int cnt[NEXP], offp[NEXP], cntp[NEXP], cur[NEXP];
    int tid = threadIdx.x;
    if (tid < NEXP) cnt[tid] = 0;
    __syncthreads();
    for (int i = tid; i < NTOK * 2; i += 256) atomicAdd(&cnt[g_top[i]], 1);
    __syncthreads();
    if (tid == 0) {
        int o = 0;
        for (int e = 0; e < NEXP; e++) {
            offp[e] = o;
            cntp[e] = ((cnt[e] + 127) >> 7) << 7;   // pad to 128
            cur[e]  = o;
            g_off_pad[e] = o;
            g_cnt_pad[e] = cntp[e];
            o += cntp[e];
        }
    }
    __syncthreads();
    for (int i = tid; i < NTOK * 2; i += 256) {
        int e = g_top[i];
        int s = atomicAdd(&cur[e], 1);
        g_tok_of_slot[s] = i >> 1;
        g_w_of_slot[s]   = g_topw[i];
        g_slot_of_tok[i] = s;
    }
    __syncthreads();
    for (int e = 0; e < NEXP; e++) {
        int start = offp[e] + cnt[e];
        int end   = offp[e] + cntp[e];
        for (int i = start + tid; i < end; i += 256) {
            g_tok_of_slot[i] = 0;
            g_w_of_slot[i]   = 0.0f;
        }
    }
}

__global__ __launch_bounds__(256)
void k_silu_mul(const float* __restrict__ A, const float* __restrict__ Bm,
                float* __restrict__ O, int n)
{
    int i = blockIdx.x * 256 + threadIdx.x;
    int stride = gridDim.x * 256;
    for (; i < n; i += stride) O[i] = A[i] * siluf(Bm[i]);
}

__global__ __launch_bounds__(256)
void k_combine(const float* __restrict__ SOUT, const float* __restrict__ CT,
               float* __restrict__ OUT)
{
    int n = blockIdx.x;
    int s0 = g_slot_of_tok[n*2], s1 = g_slot_of_tok[n*2 + 1];
    const float4* a  = (const float4*)(SOUT + (size_t)n  * CDIM);
    const float4* c0 = (const float4*)(CT   + (size_t)s0 * CDIM);
    const float4* c1 = (const float4*)(CT   + (size_t)s1 * CDIM);
    float4* o = (float4*)(OUT + (size_t)n * CDIM);
    int i = threadIdx.x;
    float4 va = a[i], v0 = c0[i], v1 = c1[i];
    o[i] = make_float4(va.x + v0.x + v1.x, va.y + v0.y + v1.y,
                       va.z + v0.z + v1.z, va.w + v0.w + v1.w);
}

// ---------------- launch ----------------
extern "C" void kernel_launch(void* const* d_in, const int* in_sizes, int n_in,
                              void* d_out, int out_size)
{
    const float* x    = (const float*)d_in[0];
    const float* ga   = (const float*)d_in[1];
    const float* wq   = (const float*)d_in[2];
    const float* wkvd = (const float*)d_in[3];
    const float* wku  = (const float*)d_in[4];
    const float* wvu  = (const float*)d_in[5];
    const float* wo   = (const float*)d_in[6];
    const float* gm   = (const float*)d_in[7];
    const float* wr   = (const float*)d_in[8];
    const float* rb   = (const float*)d_in[9];
    const float* ew1  = (const float*)d_in[10];
    const float* ew2  = (const float*)d_in[11];
    const float* ew3  = (const float*)d_in[12];
    const float* sw1  = (const float*)d_in[13];
    const float* sw2  = (const float*)d_in[14];
    const float* sw3  = (const float*)d_in[15];
    float* out = (float*)d_out;

    float *xn, *q, *kv, *sb, *att, *hb, *hn, *hid1, *hid3, *hid, *ctb;
    float *sh1, *sh3, *shid, *sout;
    cudaGetSymbolAddress((void**)&xn,   g_xn);
    cudaGetSymbolAddress((void**)&q,    g_q);
    cudaGetSymbolAddress((void**)&kv,   g_kv);
    cudaGetSymbolAddress((void**)&sb,   g_s);
    cudaGetSymbolAddress((void**)&att,  g_att);
    cudaGetSymbolAddress((void**)&hb,   g_h);
    cudaGetSymbolAddress((void**)&hn,   g_hn);
    cudaGetSymbolAddress((void**)&hid1, g_hid1);
    cudaGetSymbolAddress((void**)&hid3, g_hid3);
    cudaGetSymbolAddress((void**)&hid,  g_hid);
    cudaGetSymbolAddress((void**)&ctb,  g_ctb);
    cudaGetSymbolAddress((void**)&sh1,  g_sh1);
    cudaGetSymbolAddress((void**)&sh3,  g_sh3);
    cudaGetSymbolAddress((void**)&shid, g_shid);
    cudaGetSymbolAddress((void**)&sout, g_sout);

    // ---- attention ----
    k_rmsnorm<<<NTOK, 256>>>(x, ga, xn);
    gemm_tc<M_PLAIN, 128><<<dim3(8, 32), 256>>>(xn, 1024, wq,   1024, nullptr, q,  1024, nullptr, 1024);
    gemm_tc<M_PLAIN, 128><<<dim3(4, 32), 256>>>(xn, 1024, wkvd, 512,  nullptr, kv, 512,  nullptr, 1024);
    gemm_tc<M_KVUP,  128><<<dim3(1, 32), 256>>>(kv, 512,  wku,  64,   wvu,     nullptr, 0, nullptr, 512);
    gemm_tc<M_SCORES,128><<<dim3(8, 8, 64), 256>>>(nullptr, 0, nullptr, 0, nullptr, nullptr, 0, nullptr, 64);
    k_softmax<<<dim3(1024, 64), 256>>>(sb);
    gemm_tc<M_PV,    64><<<dim3(1, 8, 64), 256>>>(nullptr, 0, nullptr, 0, nullptr, nullptr, 0, nullptr, 0);
    gemm_tc<M_RESID, 128><<<dim3(8, 32), 256>>>(att, 1024, wo, 1024, nullptr, hb, 1024, x, 1024);

    // ---- MoE ----
    k_rmsnorm<<<NTOK, 256>>>(hb, gm, hn);
    k_router<<<NTOK/4, 128>>>(hn, wr, rb);
    k_place<<<1, 256>>>();
    gemm_tc<M_EXPUP, 128><<<dim3(8, 33, NEXP), 256>>>(nullptr, 0, ew1, FDIM, nullptr, hid1, FDIM, nullptr, CDIM);
    gemm_tc<M_EXPUP, 128><<<dim3(8, 33, NEXP), 256>>>(nullptr, 0, ew3, FDIM, nullptr, hid3, FDIM, nullptr, CDIM);
    k_silu_mul<<<1024, 256>>>(hid1, hid3, hid, MAXSLOT * FDIM);
    gemm_tc<M_EXPDOWN, 128><<<dim3(8, 33, NEXP), 256>>>(nullptr, 0, ew2, CDIM, nullptr, nullptr, 0, nullptr, FDIM);
    gemm_tc<M_PLAIN, 128><<<dim3(16, 32), 256>>>(hn, 1024, sw1, FSH, nullptr, sh1, FSH, nullptr, 1024);
    gemm_tc<M_PLAIN, 128><<<dim3(16, 32), 256>>>(hn, 1024, sw3, FSH, nullptr, sh3, FSH, nullptr, 1024);
    k_silu_mul<<<1024, 256>>>(sh1, sh3, shid, NTOK * FSH);
    gemm_tc<M_RESID, 128><<<dim3(8, 32), 256>>>(shid, FSH, sw2, 1024, nullptr, sout, 1024, hb, FSH);
    k_combine<<<NTOK, 256>>>(sout, ctb, out);
}

// round 4
// speedup vs baseline: 2.6851x; 1.1606x over previous
#include <cuda_runtime.h>
#include <math.h>
#include <stdint.h>

// ---------------- problem dims ----------------
#define NTOK 4096
#define CDIM 1024
#define HD 64
#define LAT 512
#define NEXP 8
#define FDIM 1024
#define FSH 2048
#define MAXSLOT 9216

// ---------------- scratch ----------------
__device__ float g_xn [NTOK*CDIM];
__device__ float g_q  [NTOK*CDIM];
__device__ float g_kv [NTOK*LAT];
__device__ float g_k  [NTOK*HD];
__device__ float g_v  [NTOK*HD];
__device__ float g_att[NTOK*CDIM];
__device__ float g_h  [NTOK*CDIM];
__device__ float g_hn [NTOK*CDIM];
__device__ int   g_top[NTOK*2];
__device__ float g_topw[NTOK*2];
__device__ int   g_tok_of_slot[MAXSLOT];
__device__ float g_w_of_slot[MAXSLOT];
__device__ int   g_slot_of_tok[NTOK*2];
__device__ int   g_off_pad[NEXP];
__device__ int   g_cnt_pad[NEXP];
__device__ float g_hid [MAXSLOT*FDIM];
__device__ float g_ctb [MAXSLOT*CDIM];
__device__ float g_shid[NTOK*FSH];
__device__ float g_sout[NTOK*CDIM];

// ---------------- helpers ----------------
__device__ __forceinline__ float siluf(float x) { return x / (1.0f + expf(-x)); }

__device__ __forceinline__ unsigned f2tf(float f) {
    unsigned u; asm("cvt.rna.tf32.f32 %0, %1;" : "=r"(u) : "f"(f)); return u;
}

#define MMA_TF32R(d, a, b) asm volatile( \
  "mma.sync.aligned.m16n8k8.row.col.f32.tf32.tf32.f32 " \
  "{%0,%1,%2,%3}, {%4,%5,%6,%7}, {%8,%9}, {%0,%1,%2,%3};" \
  : "+f"(d[0]), "+f"(d[1]), "+f"(d[2]), "+f"(d[3]) \
  : "r"(a[0]), "r"(a[1]), "r"(a[2]), "r"(a[3]), "r"(b[0]), "r"(b[1]))

__device__ __forceinline__ float block_reduce_sum256(float v) {
    __shared__ float sm[8];
    __syncthreads();
    int lane = threadIdx.x & 31, w = threadIdx.x >> 5;
    #pragma unroll
    for (int o = 16; o; o >>= 1) v += __shfl_xor_sync(0xffffffffu, v, o);
    if (lane == 0) sm[w] = v;
    __syncthreads();
    float r = (threadIdx.x < 8) ? sm[threadIdx.x] : 0.0f;
    if (w == 0) {
        #pragma unroll
        for (int o = 4; o; o >>= 1) r += __shfl_xor_sync(0xffffffffu, r, o);
        if (lane == 0) sm[0] = r;
    }
    __syncthreads();
    return sm[0];
}

// ---------------- flash attention (tf32 mma, online softmax) ----------------
// grid (8 qtiles, 64 bh), 256 threads, 173056 B dynamic smem
#define FA_BYTES 173056

__global__ __launch_bounds__(256)
void k_flash(const float* __restrict__ Qg, const float* __restrict__ Kg,
             const float* __restrict__ Vg, float* __restrict__ Og)
{
    extern __shared__ float fsm[];
    float* sQ  = fsm;            // [128][68] tf32
    float* sKt = fsm + 8704;     // [64][132] tf32 (transposed K)
    float* sV  = fsm + 17152;    // [128][68] tf32
    float* sP  = fsm + 25856;    // [128][132] tf32
    float* sRM = fsm + 42752;    // [2][128]
    float* sRS = fsm + 43008;    // [2][128]
    unsigned* sQu  = (unsigned*)sQ;
    unsigned* sKtu = (unsigned*)sKt;
    unsigned* sVu  = (unsigned*)sV;
    unsigned* sPu  = (unsigned*)sP;

    const int qt = blockIdx.x, bh = blockIdx.y;
    const int b = bh >> 4, hh = bh & 15;
    const int tid = threadIdx.x, warp = tid >> 5, lane = tid & 31;
    const int wm = warp & 3, wn = warp >> 2;
    const int grp = lane >> 2, tig = lane & 3;
    const float NEG = -1e30f;

    const float* Qb = Qg + (size_t)(b*1024 + qt*128) * 1024 + hh*64;
    #pragma unroll
    for (int t = 0; t < 8; t++) {
        int idx = tid + t*256;
        int r = idx >> 4, dq = idx & 15;
        float4 v = *(const float4*)(Qb + (size_t)r*1024 + dq*4);
        unsigned* p = &sQu[r*68 + dq*4];
        p[0]=f2tf(v.x*0.125f); p[1]=f2tf(v.y*0.125f);
        p[2]=f2tf(v.z*0.125f); p[3]=f2tf(v.w*0.125f);
    }

    float m_i[2][2] = {{NEG,NEG},{NEG,NEG}};
    float l_i[2][2] = {{0.f,0.f},{0.f,0.f}};
    float oacc[2][4][4] = {};

    for (int kt = 0; kt <= qt; kt++) {
        __syncthreads();
        const float* Kb = Kg + (size_t)(b*1024 + kt*128) * 64;
        const float* Vb = Vg + (size_t)(b*1024 + kt*128) * 64;
        #pragma unroll
        for (int t = 0; t < 8; t++) {
            int idx = tid + t*256;
            int s = idx >> 4, dq = idx & 15;
            int d = dq*4;
            float4 k4 = *(const float4*)(Kb + s*64 + d);
            sKtu[(d+0)*132 + s] = f2tf(k4.x);
            sKtu[(d+1)*132 + s] = f2tf(k4.y);
            sKtu[(d+2)*132 + s] = f2tf(k4.z);
            sKtu[(d+3)*132 + s] = f2tf(k4.w);
            float4 v4 = *(const float4*)(Vb + s*64 + d);
            unsigned* p = &sVu[s*68 + d];
            p[0]=f2tf(v4.x); p[1]=f2tf(v4.y); p[2]=f2tf(v4.z); p[3]=f2tf(v4.w);
        }
        __syncthreads();

        // S = Q K^T  (128x128, K=64)
        float sacc[2][8][4] = {};
        #pragma unroll
        for (int k8 = 0; k8 < 64; k8 += 8) {
            unsigned aF[2][4], bF[8][2];
            #pragma unroll
            for (int j = 0; j < 8; j++) {
                int n = wn*64 + j*8 + grp;
                bF[j][0] = sKtu[(k8+tig)*132 + n];
                bF[j][1] = sKtu[(k8+4+tig)*132 + n];
            }
            #pragma unroll
            for (int i = 0; i < 2; i++) {
                int m = wm*32 + i*16 + grp;
                aF[i][0] = sQu[m*68 + k8 + tig];
                aF[i][1] = sQu[(m+8)*68 + k8 + tig];
                aF[i][2] = sQu[m*68 + k8 + 4 + tig];
                aF[i][3] = sQu[(m+8)*68 + k8 + 4 + tig];
            }
            #pragma unroll
            for (int i = 0; i < 2; i++)
                #pragma unroll
                for (int j = 0; j < 8; j++)
                    MMA_TF32R(sacc[i][j], aF[i], bF[j]);
        }

        if (kt == qt) {   // causal mask on diagonal tile
            #pragma unroll
            for (int i = 0; i < 2; i++)
                #pragma unroll
                for (int h2 = 0; h2 < 2; h2++) {
                    int row = wm*32 + i*16 + grp + h2*8;
                    #pragma unroll
                    for (int j = 0; j < 8; j++) {
                        int col = wn*64 + j*8 + 2*tig;
                        if (col   > row) sacc[i][j][h2*2]   = NEG;
                        if (col+1 > row) sacc[i][j][h2*2+1] = NEG;
                    }
                }
        }

        // row max (quad shfl + cross-nwarp via smem)
        #pragma unroll
        for (int i = 0; i < 2; i++)
            #pragma unroll
            for (int h2 = 0; h2 < 2; h2++) {
                float v = NEG;
                #pragma unroll
                for (int j = 0; j < 8; j++)
                    v = fmaxf(v, fmaxf(sacc[i][j][h2*2], sacc[i][j][h2*2+1]));
                v = fmaxf(v, __shfl_xor_sync(0xffffffffu, v, 1));
                v = fmaxf(v, __shfl_xor_sync(0xffffffffu, v, 2));
                if (tig == 0) sRM[wn*128 + wm*32 + i*16 + grp + h2*8] = v;
            }
        __syncthreads();

        // rescale O/l, compute P, row sums
        #pragma unroll
        for (int i = 0; i < 2; i++)
            #pragma unroll
            for (int h2 = 0; h2 < 2; h2++) {
                int row = wm*32 + i*16 + grp + h2*8;
                float mnew = fmaxf(m_i[i][h2], fmaxf(sRM[row], sRM[128+row]));
                float fac = __expf(m_i[i][h2] - mnew);
                m_i[i][h2] = mnew;
                l_i[i][h2] *= fac;
                #pragma unroll
                for (int j = 0; j < 4; j++) {
                    oacc[i][j][h2*2]   *= fac;
                    oacc[i][j][h2*2+1] *= fac;
                }
                float rs = 0.0f;
                #pragma unroll
                for (int j = 0; j < 8; j++) {
                    float p0 = __expf(sacc[i][j][h2*2]   - mnew);
                    float p1 = __expf(sacc[i][j][h2*2+1] - mnew);
                    rs += p0 + p1;
                    int col = wn*64 + j*8 + 2*tig;
                    sPu[row*132 + col]     = f2tf(p0);
                    sPu[row*132 + col + 1] = f2tf(p1);
                }
                rs += __shfl_xor_sync(0xffffffffu, rs, 1);
                rs += __shfl_xor_sync(0xffffffffu, rs, 2);
                if (tig == 0) sRS[wn*128 + row] = rs;
            }
        __syncthreads();
        #pragma unroll
        for (int i = 0; i < 2; i++)
            #pragma unroll
            for (int h2 = 0; h2 < 2; h2++) {
                int row = wm*32 + i*16 + grp + h2*8;
                l_i[i][h2] += sRS[row] + sRS[128 + row];
            }

        // O += P (128x128) @ V (128x64)
        #pragma unroll
        for (int k8 = 0; k8 < 128; k8 += 8) {
            unsigned aF[2][4], bF[4][2];
            #pragma unroll
            for (int j = 0; j < 4; j++) {
                int n = wn*32 + j*8 + grp;
                bF[j][0] = sVu[(k8+tig)*68 + n];
                bF[j][1] = sVu[(k8+4+tig)*68 + n];
            }
            #pragma unroll
            for (int i = 0; i < 2; i++) {
                int m = wm*32 + i*16 + grp;
                aF[i][0] = sPu[m*132 + k8 + tig];
                aF[i][1] = sPu[(m+8)*132 + k8 + tig];
                aF[i][2] = sPu[m*132 + k8 + 4 + tig];
                aF[i][3] = sPu[(m+8)*132 + k8 + 4 + tig];
            }
            #pragma unroll
            for (int i = 0; i < 2; i++)
                #pragma unroll
                for (int j = 0; j < 4; j++)
                    MMA_TF32R(oacc[i][j], aF[i], bF[j]);
        }
    }

    float* Ob = Og + (size_t)(b*1024 + qt*128) * 1024 + hh*64;
    #pragma unroll
    for (int i = 0; i < 2; i++)
        #pragma unroll
        for (int h2 = 0; h2 < 2; h2++) {
            int row = wm*32 + i*16 + grp + h2*8;
            float inv = 1.0f / l_i[i][h2];
            #pragma unroll
            for (int j = 0; j < 4; j++) {
                int col = wn*32 + j*8 + 2*tig;
                *(float2*)(Ob + (size_t)row*1024 + col) =
                    make_float2(oacc[i][j][h2*2]*inv, oacc[i][j][h2*2+1]*inv);
            }
        }
}

// ---------------- tf32 mma GEMM (all projections / MoE) ----------------
enum { M_PLAIN = 0, M_RESID, M_KVUP, M_DUAL, M_EXPDUAL, M_EXPDOWN };

template<int MODE, int BN>
__global__ __launch_bounds__(256)
void gemm_tc(const float* __restrict__ Aa, int lda,
             const float* __restrict__ Ba, int ldb,
             const float* __restrict__ B2a,
             float* __restrict__ Ca, int ldc,
             const float* __restrict__ Da, int K)
{
    constexpr bool DUAL = (MODE == M_DUAL || MODE == M_EXPDUAL);
    constexpr int SAS = 20;
    constexpr int SBS = BN + 8;
    constexpr int NT  = BN / 16;
    constexpr int NCH = BN / 4;
    constexpr int TB  = (BN * 4) / 256;
    __shared__ unsigned sA[2][128 * SAS];
    __shared__ unsigned sB1[2][16 * SBS];
    __shared__ unsigned sB3[DUAL ? 2 : 1][DUAL ? 16 * SBS : 4];

    const int tid = threadIdx.x;
    const int nb = blockIdx.x, mb = blockIdx.y, z = blockIdx.z;
    const int m0 = mb * 128, n0 = nb * BN;

    const float* A = Aa; const float* B1 = Ba; const float* B3 = B2a;
    float* C = Ca; const float* wrow = nullptr; const int* ridx = nullptr;
    int ldcx = ldc;

    if (MODE == M_EXPDUAL) {
        if (m0 >= g_cnt_pad[z]) return;
        int off = g_off_pad[z];
        ridx = g_tok_of_slot + off;
        A = g_hn; lda = CDIM;
        B1 = Ba + (size_t)z * CDIM * FDIM;
        B3 = B2a + (size_t)z * CDIM * FDIM;
        C = Ca + (size_t)off * FDIM; ldcx = FDIM;
    } else if (MODE == M_EXPDOWN) {
        if (m0 >= g_cnt_pad[z]) return;
        int off = g_off_pad[z];
        A = g_hid + (size_t)off * FDIM; lda = FDIM;
        B1 = Ba + (size_t)z * FDIM * CDIM;
        C = g_ctb + (size_t)off * CDIM; ldcx = CDIM;
        wrow = g_w_of_slot + off;
    }

    const int lane = tid & 31, warp = tid >> 5;
    const int wm = warp & 3, wn = warp >> 2;
    const int mw = wm * 32, nw = wn * (BN / 2);
    const int grp = lane >> 2, tig = lane & 3;

    float acc1[2][NT][4] = {};
    float acc3[2][DUAL ? NT : 1][4] = {};

    auto LDGA = [&](float4 (&r)[2], int k0) {
        #pragma unroll
        for (int t = 0; t < 2; t++) {
            int c = tid + 256 * t;
            int row = c >> 2, kc = c & 3;
            int gr = (MODE == M_EXPDUAL) ? ridx[m0 + row] : (m0 + row);
            r[t] = *(const float4*)(A + (size_t)gr * lda + k0 + kc * 4);
        }
    };
    auto STSA = [&](const float4 (&r)[2], int s) {
        #pragma unroll
        for (int t = 0; t < 2; t++) {
            int c = tid + 256 * t;
            int row = c >> 2, kc = c & 3;
            uint4 u = make_uint4(f2tf(r[t].x), f2tf(r[t].y), f2tf(r[t].z), f2tf(r[t].w));
            *(uint4*)&sA[s][row * SAS + kc * 4] = u;
        }
    };
    auto LDGB = [&](float4 (&r1)[TB], float4 (&r3)[TB], int k0) {
        #pragma unroll
        for (int t = 0; t < TB; t++) {
            int c = tid + 256 * t;
            int krow = c / NCH, nc = c % NCH;
            if (MODE == M_KVUP) {
                const float* bs = (nc < 16) ? B1 : B3;
                r1[t] = *(const float4*)(bs + (size_t)(k0 + krow) * 64 + (nc & 15) * 4);
            } else {
                r1[t] = *(const float4*)(B1 + (size_t)(k0 + krow) * ldb + n0 + nc * 4);
                if (DUAL)
                    r3[t] = *(const float4*)(B3 + (size_t)(k0 + krow) * ldb + n0 + nc * 4);
            }
        }
    };
    auto STSB = [&](const float4 (&r1)[TB], const float4 (&r3)[TB], int s) {
        #pragma unroll
        for (int t = 0; t < TB; t++) {
            int c = tid + 256 * t;
            int krow = c / NCH, nc = c % NCH;
            uint4 u = make_uint4(f2tf(r1[t].x), f2tf(r1[t].y), f2tf(r1[t].z), f2tf(r1[t].w));
            *(uint4*)&sB1[s][krow * SBS + nc * 4] = u;
            if (DUAL) {
                uint4 u3 = make_uint4(f2tf(r3[t].x), f2tf(r3[t].y), f2tf(r3[t].z), f2tf(r3[t].w));
                *(uint4*)&sB3[s][krow * SBS + nc * 4] = u3;
            }
        }
    };
    auto COMP = [&](int s) {
        #pragma unroll
        for (int k8 = 0; k8 < 16; k8 += 8) {
            unsigned bF1[NT][2], bF3[DUAL ? NT : 1][2], aF[2][4];
            #pragma unroll
            for (int j = 0; j < NT; j++) {
                int n = nw + j * 8 + grp;
                bF1[j][0] = sB1[s][(k8 + tig) * SBS + n];
                bF1[j][1] = sB1[s][(k8 + 4 + tig) * SBS + n];
                if (DUAL) {
                    bF3[j][0] = sB3[s][(k8 + tig) * SBS + n];
                    bF3[j][1] = sB3[s][(k8 + 4 + tig) * SBS + n];
                }
            }
            #pragma unroll
            for (int i = 0; i < 2; i++) {
                int m = mw + i * 16 + grp;
                aF[i][0] = sA[s][m * SAS + k8 + tig];
                aF[i][1] = sA[s][(m + 8) * SAS + k8 + tig];
                aF[i][2] = sA[s][m * SAS + k8 + 4 + tig];
                aF[i][3] = sA[s][(m + 8) * SAS + k8 + 4 + tig];
            }
            #pragma unroll
            for (int i = 0; i < 2; i++)
                #pragma unroll
                for (int j = 0; j < NT; j++) {
                    MMA_TF32R(acc1[i][j], aF[i], bF1[j]);
                    if (DUAL) MMA_TF32R(acc3[i][j], aF[i], bF3[j]);
                }
        }
    };

    const int KT = K >> 4;
    float4 ra[2]; float4 rb1[TB]; float4 rb3[TB];
    LDGA(ra, 0); LDGB(rb1, rb3, 0);
    STSA(ra, 0); STSB(rb1, rb3, 0);
    __syncthreads();
    for (int kt = 0; kt < KT; kt++) {
        int cur = kt & 1;
        bool more = (kt + 1 < KT);
        if (more) { LDGA(ra, (kt + 1) * 16); LDGB(rb1, rb3, (kt + 1) * 16); }
        COMP(cur);
        __syncthreads();
        if (more) { STSA(ra, cur ^ 1); STSB(rb1, rb3, cur ^ 1); __syncthreads(); }
    }

    #pragma unroll
    for (int i = 0; i < 2; i++) {
        #pragma unroll
        for (int j = 0; j < NT; j++) {
            #pragma unroll
            for (int hh = 0; hh < 2; hh++) {
                int ml = mw + i * 16 + grp + hh * 8;
                int nl = nw + j * 8 + 2 * tig;
                float v0 = acc1[i][j][hh * 2 + 0];
                float v1 = acc1[i][j][hh * 2 + 1];
                int gm = m0 + ml, gn = n0 + nl;
                if (DUAL) {
                    v0 = v0 * siluf(acc3[i][j][hh * 2 + 0]);
                    v1 = v1 * siluf(acc3[i][j][hh * 2 + 1]);
                    *(float2*)(C + (size_t)gm * ldcx + gn) = make_float2(v0, v1);
                } else if (MODE == M_KVUP) {
                    if (nl < 64) *(float2*)(g_k + (size_t)gm * 64 + nl) = make_float2(v0, v1);
                    else         *(float2*)(g_v + (size_t)gm * 64 + nl - 64) = make_float2(v0, v1);
                } else if (MODE == M_EXPDOWN) {
                    float w = wrow[gm];
                    *(float2*)(C + (size_t)gm * ldcx + gn) = make_float2(v0 * w, v1 * w);
                } else if (MODE == M_RESID) {
                    float2 d = *(const float2*)(Da + (size_t)gm * ldcx + gn);
                    *(float2*)(C + (size_t)gm * ldcx + gn) = make_float2(v0 + d.x, v1 + d.y);
                } else {
                    *(float2*)(C + (size_t)gm * ldcx + gn) = make_float2(v0, v1);
                }
            }
        }
    }
}

// ---------------- elementwise / small kernels ----------------
__global__ __launch_bounds__(256)
void k_rmsnorm(const float* __restrict__ X, const float* __restrict__ G,
               float* __restrict__ O)
{
    int n = blockIdx.x;
    const float4* x4 = (const float4*)(X + (size_t)n * CDIM);
    const float4* g4 = (const float4*)G;
    float4 v = x4[threadIdx.x];
    float ss = v.x*v.x + v.y*v.y + v.z*v.z + v.w*v.w;
    float tot = block_reduce_sum256(ss);
    float r = 1.0f / sqrtf(tot * (1.0f / CDIM) + 1e-6f);
    float4 g = g4[threadIdx.x];
    ((float4*)(O + (size_t)n * CDIM))[threadIdx.x] =
        make_float4(v.x*r*g.x, v.y*r*g.y, v.z*r*g.z, v.w*r*g.w);
}

__global__ __launch_bounds__(128)
void k_router(const float* __restrict__ HN, const float* __restrict__ WR,
              const float* __restrict__ RB)
{
    int n = blockIdx.x * 4 + (threadIdx.x >> 5);
    int lane = threadIdx.x & 31;
    const float* x = HN + (size_t)n * CDIM;
    float p[NEXP] = {};
    for (int c = lane; c < CDIM; c += 32) {
        float xv = x[c];
        #pragma unroll
        for (int e = 0; e < NEXP; e++) p[e] += xv * WR[c * NEXP + e];
    }
    #pragma unroll
    for (int e = 0; e < NEXP; e++) {
        #pragma unroll
        for (int o = 16; o; o >>= 1)
            p[e] += __shfl_xor_sync(0xffffffffu, p[e], o);
    }
    if (lane == 0) {
        float logit[NEXP], biased[NEXP];
        #pragma unroll
        for (int e = 0; e < NEXP; e++) {
            logit[e]  = p[e] * 0.03125f;
            biased[e] = logit[e] + RB[e];
        }
        int i0 = 0;
        #pragma unroll
        for (int e = 1; e < NEXP; e++) if (biased[e] > biased[i0]) i0 = e;
        int i1 = -1;
        #pragma unroll
        for (int e = 0; e < NEXP; e++) {
            if (e == i0) continue;
            if (i1 < 0 || biased[e] > biased[i1]) i1 = e;
        }
        float m  = fmaxf(logit[i0], logit[i1]);
        float e0 = expf(logit[i0] - m), e1 = expf(logit[i1] - m);
        float inv = 1.0f / (e0 + e1);
        g_top [n*2]     = i0; g_top [n*2 + 1] = i1;
        g_topw[n*2]     = e0 * inv;
        g_topw[n*2 + 1] = e1 * inv;
    }
}

__global__ __launch_bounds__(256)
void k_place()
{
    __shared__ int cnt[NEXP], offp[NEXP], cntp[NEXP], cur[NEXP];
    int tid = threadIdx.x;
    if (tid < NEXP) cnt[tid] = 0;
    __syncthreads();
    for (int i = tid; i < NTOK * 2; i += 256) atomicAdd(&cnt[g_top[i]], 1);
    __syncthreads();
    if (tid == 0) {
        int o = 0;
        for (int e = 0; e < NEXP; e++) {
            offp[e] = o;
            cntp[e] = ((cnt[e] + 127) >> 7) << 7;
            cur[e]  = o;
            g_off_pad[e] = o;
            g_cnt_pad[e] = cntp[e];
            o += cntp[e];
        }
    }
    __syncthreads();
    for (int i = tid; i < NTOK * 2; i += 256) {
        int e = g_top[i];
        int s = atomicAdd(&cur[e], 1);
        g_tok_of_slot[s] = i >> 1;
        g_w_of_slot[s]   = g_topw[i];
        g_slot_of_tok[i] = s;
    }
    __syncthreads();
    for (int e = 0; e < NEXP; e++) {
        int start = offp[e] + cnt[e];
        int end   = offp[e] + cntp[e];
        for (int i = start + tid; i < end; i += 256) {
            g_tok_of_slot[i] = 0;
            g_w_of_slot[i]   = 0.0f;
        }
    }
}

__global__ __launch_bounds__(256)
void k_combine(const float* __restrict__ SOUT, const float* __restrict__ CT,
               float* __restrict__ OUT)
{
    int n = blockIdx.x;
    int s0 = g_slot_of_tok[n*2], s1 = g_slot_of_tok[n*2 + 1];
    const float4* a  = (const float4*)(SOUT + (size_t)n  * CDIM);
    const float4* c0 = (const float4*)(CT   + (size_t)s0 * CDIM);
    const float4* c1 = (const float4*)(CT   + (size_t)s1 * CDIM);
    float4* o = (float4*)(OUT + (size_t)n * CDIM);
    int i = threadIdx.x;
    float4 va = a[i], v0 = c0[i], v1 = c1[i];
    o[i] = make_float4(va.x + v0.x + v1.x, va.y + v0.y + v1.y,
                       va.z + v0.z + v1.z, va.w + v0.w + v1.w);
}

// ---------------- launch ----------------
extern "C" void kernel_launch(void* const* d_in, const int* in_sizes, int n_in,
                              void* d_out, int out_size)
{
    const float* x    = (const float*)d_in[0];
    const float* ga   = (const float*)d_in[1];
    const float* wq   = (const float*)d_in[2];
    const float* wkvd = (const float*)d_in[3];
    const float* wku  = (const float*)d_in[4];
    const float* wvu  = (const float*)d_in[5];
    const float* wo   = (const float*)d_in[6];
    const float* gm   = (const float*)d_in[7];
    const float* wr   = (const float*)d_in[8];
    const float* rb   = (const float*)d_in[9];
    const float* ew1  = (const float*)d_in[10];
    const float* ew2  = (const float*)d_in[11];
    const float* ew3  = (const float*)d_in[12];
    const float* sw1  = (const float*)d_in[13];
    const float* sw2  = (const float*)d_in[14];
    const float* sw3  = (const float*)d_in[15];
    float* out = (float*)d_out;

    float *xn, *q, *kv, *kb, *vb, *att, *hb, *hn, *hid, *ctb, *shid, *sout;
    cudaGetSymbolAddress((void**)&xn,   g_xn);
    cudaGetSymbolAddress((void**)&q,    g_q);
    cudaGetSymbolAddress((void**)&kv,   g_kv);
    cudaGetSymbolAddress((void**)&kb,   g_k);
    cudaGetSymbolAddress((void**)&vb,   g_v);
    cudaGetSymbolAddress((void**)&att,  g_att);
    cudaGetSymbolAddress((void**)&hb,   g_h);
    cudaGetSymbolAddress((void**)&hn,   g_hn);
    cudaGetSymbolAddress((void**)&hid,  g_hid);
    cudaGetSymbolAddress((void**)&ctb,  g_ctb);
    cudaGetSymbolAddress((void**)&shid, g_shid);
    cudaGetSymbolAddress((void**)&sout, g_sout);

    cudaFuncSetAttribute(k_flash, cudaFuncAttributeMaxDynamicSharedMemorySize, FA_BYTES);

    // ---- attention ----
    k_rmsnorm<<<NTOK, 256>>>(x, ga, xn);
    gemm_tc<M_PLAIN, 128><<<dim3(8, 32), 256>>>(xn, 1024, wq,   1024, nullptr, q,  1024, nullptr, 1024);
    gemm_tc<M_PLAIN, 128><<<dim3(4, 32), 256>>>(xn, 1024, wkvd, 512,  nullptr, kv, 512,  nullptr, 1024);
    gemm_tc<M_KVUP, 128><<<dim3(1, 32), 256>>>(kv, 512, wku, 64, wvu, nullptr, 0, nullptr, 512);
    k_flash<<<dim3(8, 64), 256, FA_BYTES>>>(q, kb, vb, att);
    gemm_tc<M_RESID, 128><<<dim3(8, 32), 256>>>(att, 1024, wo, 1024, nullptr, hb, 1024, x, 1024);

    // ---- MoE ----
    k_rmsnorm<<<NTOK, 256>>>(hb, gm, hn);
    k_router<<<NTOK/4, 128>>>(hn, wr, rb);
    k_place<<<1, 256>>>();
    gemm_tc<M_EXPDUAL, 64><<<dim3(16, 72, NEXP), 256>>>(nullptr, 0, ew1, FDIM, ew3, hid, FDIM, nullptr, CDIM);
    gemm_tc<M_EXPDOWN, 128><<<dim3(8, 72, NEXP), 256>>>(nullptr, 0, ew2, CDIM, nullptr, nullptr, 0, nullptr, FDIM);
    gemm_tc<M_DUAL, 64><<<dim3(32, 32), 256>>>(hn, 1024, sw1, FSH, sw3, shid, FSH, nullptr, CDIM);
    gemm_tc<M_RESID, 128><<<dim3(8, 32), 256>>>(shid, FSH, sw2, 1024, nullptr, sout, 1024, hb, FSH);
    k_combine<<<NTOK, 256>>>(sout, ctb, out);
}

// round 7
// speedup vs baseline: 2.9783x; 1.1092x over previous
#include <cuda_runtime.h>
#include <math.h>
#include <stdint.h>

// ---------------- problem dims ----------------
#define NTOK 4096
#define CDIM 1024
#define HD 64
#define LAT 512
#define NEXP 8
#define FDIM 1024
#define FSH 2048
#define MAXSLOT 9216

// ---------------- scratch ----------------
__device__ float g_xn [NTOK*CDIM];
__device__ float g_q  [NTOK*CDIM];
__device__ float g_kv [NTOK*LAT];
__device__ float g_kvo[NTOK*128];          // K|V interleaved per row
__device__ float g_att[NTOK*CDIM];
__device__ float g_h  [NTOK*CDIM];
__device__ float g_hn [NTOK*CDIM];         // tf32-rounded (GEMM operand)
__device__ float g_hnf[NTOK*CDIM];         // full fp32 (router only)
__device__ int   g_top[NTOK*2];
__device__ float g_topw[NTOK*2];
__device__ int   g_tok_of_slot[MAXSLOT];
__device__ float g_w_of_slot[MAXSLOT];
__device__ int   g_slot_of_tok[NTOK*2];
__device__ int   g_off_pad[NEXP];
__device__ int   g_cnt_pad[NEXP];
__device__ float g_hid [MAXSLOT*FDIM];
__device__ float g_ctb [MAXSLOT*CDIM];
__device__ float g_shid[NTOK*FSH];
__device__ float g_sout[NTOK*CDIM];

// tf32-rounded weights
__device__ float g_wqkv_r[CDIM*1536];
__device__ float g_wkv_r [LAT*128];
__device__ float g_wo_r  [CDIM*CDIM];
__device__ float g_sw1_r [CDIM*FSH];
__device__ float g_sw3_r [CDIM*FSH];
__device__ float g_sw2_r [FSH*CDIM];
__device__ float g_ew1_r [NEXP*CDIM*FDIM];
__device__ float g_ew2_r [NEXP*FDIM*CDIM];
__device__ float g_ew3_r [NEXP*CDIM*FDIM];

// ---------------- helpers ----------------
__device__ __forceinline__ float siluf(float x) { return x / (1.0f + expf(-x)); }

__device__ __forceinline__ unsigned f2tf(float f) {
    unsigned u; asm("cvt.rna.tf32.f32 %0, %1;" : "=r"(u) : "f"(f)); return u;
}
__device__ __forceinline__ float rtf(float f) { return __uint_as_float(f2tf(f)); }

__device__ __forceinline__ uint32_t smem_u32(const void* p) {
    uint32_t a;
    asm("{ .reg .u64 t; cvta.to.shared.u64 t, %1; cvt.u32.u64 %0, t; }" : "=r"(a) : "l"(p));
    return a;
}
__device__ __forceinline__ void cpa16(uint32_t saddr, const float* g) {
    asm volatile("cp.async.cg.shared.global [%0], [%1], 16;" :: "r"(saddr), "l"(g));
}
#define CP_COMMIT() asm volatile("cp.async.commit_group;" ::: "memory")
#define CP_WAIT1()  asm volatile("cp.async.wait_group 1;" ::: "memory")

#define MMA_TF32R(d, a, b) asm volatile( \
  "mma.sync.aligned.m16n8k8.row.col.f32.tf32.tf32.f32 " \
  "{%0,%1,%2,%3}, {%4,%5,%6,%7}, {%8,%9}, {%0,%1,%2,%3};" \
  : "+f"(d[0]), "+f"(d[1]), "+f"(d[2]), "+f"(d[3]) \
  : "r"(a[0]), "r"(a[1]), "r"(a[2]), "r"(a[3]), "r"(b[0]), "r"(b[1]))

__device__ __forceinline__ float block_reduce_sum256(float v) {
    __shared__ float sm[8];
    __syncthreads();
    int lane = threadIdx.x & 31, w = threadIdx.x >> 5;
    #pragma unroll
    for (int o = 16; o; o >>= 1) v += __shfl_xor_sync(0xffffffffu, v, o);
    if (lane == 0) sm[w] = v;
    __syncthreads();
    float r = (threadIdx.x < 8) ? sm[threadIdx.x] : 0.0f;
    if (w == 0) {
        #pragma unroll
        for (int o = 4; o; o >>= 1) r += __shfl_xor_sync(0xffffffffu, r, o);
        if (lane == 0) sm[0] = r;
    }
    __syncthreads();
    return sm[0];
}

// ---------------- rounding copies ----------------
__global__ __launch_bounds__(256)
void k_round4(const float* __restrict__ s, float* __restrict__ d, int n4)
{
    int i = blockIdx.x * 256 + threadIdx.x;
    int st = gridDim.x * 256;
    for (; i < n4; i += st) {
        float4 v = ((const float4*)s)[i];
        ((float4*)d)[i] = make_float4(rtf(v.x), rtf(v.y), rtf(v.z), rtf(v.w));
    }
}
__global__ __launch_bounds__(256)
void k_round_str(const float* __restrict__ s, int sld,
                 float* __restrict__ d, int dld, int rows, int cols4)
{
    int i = blockIdx.x * 256 + threadIdx.x;
    int st = gridDim.x * 256;
    int n = rows * cols4;
    for (; i < n; i += st) {
        int r = i / cols4, c = i % cols4;
        float4 v = *(const float4*)(s + (size_t)r * sld + c * 4);
        *(float4*)(d + (size_t)r * dld + c * 4) =
            make_float4(rtf(v.x), rtf(v.y), rtf(v.z), rtf(v.w));
    }
}

// ---------------- cp.async tf32 GEMM (3-stage pipeline) ----------------
enum { M_PLAIN = 0, M_RESID = 1, M_DUAL = 2, M_EXPDUAL = 3, M_EXPDOWN = 4, M_QKV = 5 };

template<int MODE, int BN>
__global__ __launch_bounds__(256)
void gemm_cp(const float* __restrict__ Aa, int lda,
             const float* __restrict__ B1a, const float* __restrict__ B3a, int ldb,
             float* __restrict__ Ca, int ldc,
             const float* __restrict__ Da, int K)
{
    constexpr bool DUAL  = (MODE == M_DUAL || MODE == M_EXPDUAL);
    constexpr bool ROUND = (MODE == M_QKV || MODE == M_PLAIN || MODE == M_DUAL || MODE == M_EXPDUAL);
    constexpr int NT  = BN / 16;
    constexpr int SBS = BN + 8;
    constexpr int NCH = BN / 4;
    constexpr int TB  = BN / 64;      // 16B chunks per thread per B matrix
    extern __shared__ float dsm[];
    float* sA  = dsm;                        // 3 stages x 128x20
    float* sB1 = dsm + 3 * 128 * 20;
    float* sB3 = sB1 + (DUAL ? 3 * 16 * SBS : 0);

    const int tid = threadIdx.x;
    const int nb = blockIdx.x, mb = blockIdx.y, z = blockIdx.z;
    const int m0 = mb * 128, n0 = nb * BN;

    const float* A = Aa; const float* B1 = B1a; const float* B3 = B3a;
    float* C = Ca; const float* wrow = nullptr; const int* ridx = nullptr;
    int ldcx = ldc;

    if (MODE == M_EXPDUAL) {
        if (m0 >= g_cnt_pad[z]) return;
        int off = g_off_pad[z];
        ridx = g_tok_of_slot + off;
        A = g_hn; lda = CDIM;
        B1 = B1a + (size_t)z * CDIM * FDIM;
        B3 = B3a + (size_t)z * CDIM * FDIM;
        C = Ca + (size_t)off * FDIM; ldcx = FDIM;
    } else if (MODE == M_EXPDOWN) {
        if (m0 >= g_cnt_pad[z]) return;
        int off = g_off_pad[z];
        A = g_hid + (size_t)off * FDIM; lda = FDIM;
        B1 = B1a + (size_t)z * FDIM * CDIM;
        C = g_ctb + (size_t)off * CDIM; ldcx = CDIM;
        wrow = g_w_of_slot + off;
    }

    const int lane = tid & 31, warp = tid >> 5;
    const int wm = warp & 3, wn = warp >> 2;
    const int mw = wm * 32, nw = wn * (BN / 2);
    const int grp = lane >> 2, tig = lane & 3;

    const int aRow0 = tid >> 2, aKc = tid & 3;
    const int KT = K >> 4;

    auto ISSUE = [&](int kt, int st) {
        if (kt < KT) {
            int k0 = kt << 4;
            #pragma unroll
            for (int t = 0; t < 2; t++) {
                int row = aRow0 + t * 64;
                int gr = (MODE == M_EXPDUAL) ? ridx[m0 + row] : (m0 + row);
                cpa16(smem_u32(&sA[st * 128 * 20 + row * 20 + aKc * 4]),
                      A + (size_t)gr * lda + k0 + aKc * 4);
            }
            #pragma unroll
            for (int t = 0; t < TB; t++) {
                int c = tid + 256 * t;
                int krow = c / NCH, nc = c % NCH;
                cpa16(smem_u32(&sB1[st * 16 * SBS + krow * SBS + nc * 4]),
                      B1 + (size_t)(k0 + krow) * ldb + n0 + nc * 4);
                if (DUAL)
                    cpa16(smem_u32(&sB3[st * 16 * SBS + krow * SBS + nc * 4]),
                          B3 + (size_t)(k0 + krow) * ldb + n0 + nc * 4);
            }
        }
        CP_COMMIT();
    };

    float acc1[2][NT][4] = {};
    float acc3[2][DUAL ? NT : 1][4] = {};

    auto COMP = [&](int st) {
        const unsigned* uA  = (const unsigned*)(sA  + st * 128 * 20);
        const unsigned* uB1 = (const unsigned*)(sB1 + st * 16 * SBS);
        const unsigned* uB3 = (const unsigned*)(sB3 + st * 16 * SBS);
        #pragma unroll
        for (int k8 = 0; k8 < 16; k8 += 8) {
            unsigned bF1[NT][2], bF3[DUAL ? NT : 1][2], aF[2][4];
            #pragma unroll
            for (int j = 0; j < NT; j++) {
                int n = nw + j * 8 + grp;
                bF1[j][0] = uB1[(k8 + tig) * SBS + n];
                bF1[j][1] = uB1[(k8 + 4 + tig) * SBS + n];
                if (DUAL) {
                    bF3[j][0] = uB3[(k8 + tig) * SBS + n];
                    bF3[j][1] = uB3[(k8 + 4 + tig) * SBS + n];
                }
            }
            #pragma unroll
            for (int i = 0; i < 2; i++) {
                int m = mw + i * 16 + grp;
                aF[i][0] = uA[m * 20 + k8 + tig];
                aF[i][1] = uA[(m + 8) * 20 + k8 + tig];
                aF[i][2] = uA[m * 20 + k8 + 4 + tig];
                aF[i][3] = uA[(m + 8) * 20 + k8 + 4 + tig];
            }
            #pragma unroll
            for (int i = 0; i < 2; i++)
                #pragma unroll
                for (int j = 0; j < NT; j++) {
                    MMA_TF32R(acc1[i][j], aF[i], bF1[j]);
                    if (DUAL) MMA_TF32R(acc3[i][j], aF[i], bF3[j]);
                }
        }
    };

    ISSUE(0, 0);
    ISSUE(1, 1);
    for (int kt = 0; kt < KT; kt++) {
        int st = kt % 3;
        CP_WAIT1();
        __syncthreads();
        ISSUE(kt + 2, (kt + 2) % 3);
        COMP(st);
    }

    // epilogue
    #pragma unroll
    for (int i = 0; i < 2; i++) {
        #pragma unroll
        for (int j = 0; j < NT; j++) {
            #pragma unroll
            for (int hh = 0; hh < 2; hh++) {
                int ml = mw + i * 16 + grp + hh * 8;
                int nl = nw + j * 8 + 2 * tig;
                float v0 = acc1[i][j][hh * 2 + 0];
                float v1 = acc1[i][j][hh * 2 + 1];
                int gm = m0 + ml, gn = n0 + nl;
                if (DUAL) {
                    v0 = v0 * siluf(acc3[i][j][hh * 2 + 0]);
                    v1 = v1 * siluf(acc3[i][j][hh * 2 + 1]);
                }
                if (ROUND) { v0 = rtf(v0); v1 = rtf(v1); }
                if (MODE == M_QKV) {
                    if (gn < 1024)
                        *(float2*)(g_q + (size_t)gm * 1024 + gn) = make_float2(v0, v1);
                    else
                        *(float2*)(g_kv + (size_t)gm * 512 + gn - 1024) = make_float2(v0, v1);
                } else if (MODE == M_EXPDOWN) {
                    float w = wrow[gm];
                    *(float2*)(C + (size_t)gm * ldcx + gn) = make_float2(v0 * w, v1 * w);
                } else if (MODE == M_RESID) {
                    float2 d = *(const float2*)(Da + (size_t)gm * ldcx + gn);
                    *(float2*)(C + (size_t)gm * ldcx + gn) = make_float2(v0 + d.x, v1 + d.y);
                } else {
                    *(float2*)(C + (size_t)gm * ldcx + gn) = make_float2(v0, v1);
                }
            }
        }
    }
}

// ---------------- flash attention (tf32 mma, online softmax) ----------------
#define FA_BYTES 173056

__global__ __launch_bounds__(256)
void k_flash(const float* __restrict__ Qg, const float* __restrict__ KVg,
             float* __restrict__ Og)
{
    extern __shared__ float fsm[];
    float* sQ  = fsm;            // [128][68]
    float* sKt = fsm + 8704;     // [64][132]
    float* sV  = fsm + 17152;    // [128][68]
    float* sP  = fsm + 25856;    // [128][132]
    float* sRM = fsm + 42752;    // [2][128]
    float* sRS = fsm + 43008;    // [2][128]
    unsigned* sQu  = (unsigned*)sQ;
    unsigned* sKtu = (unsigned*)sKt;
    unsigned* sVu  = (unsigned*)sV;
    unsigned* sPu  = (unsigned*)sP;

    const int qt = blockIdx.x, bh = blockIdx.y;
    const int b = bh >> 4, hh = bh & 15;
    const int tid = threadIdx.x, warp = tid >> 5, lane = tid & 31;
    const int wm = warp & 3, wn = warp >> 2;
    const int grp = lane >> 2, tig = lane & 3;
    const float NEG = -1e30f;

    const float* Qb = Qg + (size_t)(b*1024 + qt*128) * 1024 + hh*64;
    #pragma unroll
    for (int t = 0; t < 8; t++) {
        int idx = tid + t*256;
        int r = idx >> 4, dq = idx & 15;
        float4 v = *(const float4*)(Qb + (size_t)r*1024 + dq*4);
        unsigned* p = &sQu[r*68 + dq*4];
        p[0]=f2tf(v.x*0.125f); p[1]=f2tf(v.y*0.125f);
        p[2]=f2tf(v.z*0.125f); p[3]=f2tf(v.w*0.125f);
    }

    float m_i[2][2] = {{NEG,NEG},{NEG,NEG}};
    float l_i[2][2] = {{0.f,0.f},{0.f,0.f}};
    float oacc[2][4][4] = {};

    for (int kt = 0; kt <= qt; kt++) {
        __syncthreads();
        const float* KVb = KVg + (size_t)(b*1024 + kt*128) * 128;
        #pragma unroll
        for (int t = 0; t < 8; t++) {
            int idx = tid + t*256;
            int s = idx >> 4, dq = idx & 15;
            int d = dq*4;
            float4 k4 = *(const float4*)(KVb + (size_t)s*128 + d);
            sKtu[(d+0)*132 + s] = __float_as_uint(k4.x);
            sKtu[(d+1)*132 + s] = __float_as_uint(k4.y);
            sKtu[(d+2)*132 + s] = __float_as_uint(k4.z);
            sKtu[(d+3)*132 + s] = __float_as_uint(k4.w);
            float4 v4 = *(const float4*)(KVb + (size_t)s*128 + 64 + d);
            unsigned* p = &sVu[s*68 + d];
            p[0]=__float_as_uint(v4.x); p[1]=__float_as_uint(v4.y);
            p[2]=__float_as_uint(v4.z); p[3]=__float_as_uint(v4.w);
        }
        __syncthreads();

        float sacc[2][8][4] = {};
        #pragma unroll
        for (int k8 = 0; k8 < 64; k8 += 8) {
            unsigned aF[2][4], bF[8][2];
            #pragma unroll
            for (int j = 0; j < 8; j++) {
                int n = wn*64 + j*8 + grp;
                bF[j][0] = sKtu[(k8+tig)*132 + n];
                bF[j][1] = sKtu[(k8+4+tig)*132 + n];
            }
            #pragma unroll
            for (int i = 0; i < 2; i++) {
                int m = wm*32 + i*16 + grp;
                aF[i][0] = sQu[m*68 + k8 + tig];
                aF[i][1] = sQu[(m+8)*68 + k8 + tig];
                aF[i][2] = sQu[m*68 + k8 + 4 + tig];
                aF[i][3] = sQu[(m+8)*68 + k8 + 4 + tig];
            }
            #pragma unroll
            for (int i = 0; i < 2; i++)
                #pragma unroll
                for (int j = 0; j < 8; j++)
                    MMA_TF32R(sacc[i][j], aF[i], bF[j]);
        }

        if (kt == qt) {
            #pragma unroll
            for (int i = 0; i < 2; i++)
                #pragma unroll
                for (int h2 = 0; h2 < 2; h2++) {
                    int row = wm*32 + i*16 + grp + h2*8;
                    #pragma unroll
                    for (int j = 0; j < 8; j++) {
                        int col = wn*64 + j*8 + 2*tig;
                        if (col   > row) sacc[i][j][h2*2]   = NEG;
                        if (col+1 > row) sacc[i][j][h2*2+1] = NEG;
                    }
                }
        }

        #pragma unroll
        for (int i = 0; i < 2; i++)
            #pragma unroll
            for (int h2 = 0; h2 < 2; h2++) {
                float v = NEG;
                #pragma unroll
                for (int j = 0; j < 8; j++)
                    v = fmaxf(v, fmaxf(sacc[i][j][h2*2], sacc[i][j][h2*2+1]));
                v = fmaxf(v, __shfl_xor_sync(0xffffffffu, v, 1));
                v = fmaxf(v, __shfl_xor_sync(0xffffffffu, v, 2));
                if (tig == 0) sRM[wn*128 + wm*32 + i*16 + grp + h2*8] = v;
            }
        __syncthreads();

        #pragma unroll
        for (int i = 0; i < 2; i++)
            #pragma unroll
            for (int h2 = 0; h2 < 2; h2++) {
                int row = wm*32 + i*16 + grp + h2*8;
                float mnew = fmaxf(m_i[i][h2], fmaxf(sRM[row], sRM[128+row]));
                float fac = __expf(m_i[i][h2] - mnew);
                m_i[i][h2] = mnew;
                l_i[i][h2] *= fac;
                #pragma unroll
                for (int j = 0; j < 4; j++) {
                    oacc[i][j][h2*2]   *= fac;
                    oacc[i][j][h2*2+1] *= fac;
                }
                float rs = 0.0f;
                #pragma unroll
                for (int j = 0; j < 8; j++) {
                    float p0 = __expf(sacc[i][j][h2*2]   - mnew);
                    float p1 = __expf(sacc[i][j][h2*2+1] - mnew);
                    rs += p0 + p1;
                    int col = wn*64 + j*8 + 2*tig;
                    sPu[row*132 + col]     = f2tf(p0);
                    sPu[row*132 + col + 1] = f2tf(p1);
                }
                rs += __shfl_xor_sync(0xffffffffu, rs, 1);
                rs += __shfl_xor_sync(0xffffffffu, rs, 2);
                if (tig == 0) sRS[wn*128 + row] = rs;
            }
        __syncthreads();
        #pragma unroll
        for (int i = 0; i < 2; i++)
            #pragma unroll
            for (int h2 = 0; h2 < 2; h2++) {
                int row = wm*32 + i*16 + grp + h2*8;
                l_i[i][h2] += sRS[row] + sRS[128 + row];
            }

        #pragma unroll
        for (int k8 = 0; k8 < 128; k8 += 8) {
            unsigned aF[2][4], bF[4][2];
            #pragma unroll
            for (int j = 0; j < 4; j++) {
                int n = wn*32 + j*8 + grp;
                bF[j][0] = sVu[(k8+tig)*68 + n];
                bF[j][1] = sVu[(k8+4+tig)*68 + n];
            }
            #pragma unroll
            for (int i = 0; i < 2; i++) {
                int m = wm*32 + i*16 + grp;
                aF[i][0] = sPu[m*132 + k8 + tig];
                aF[i][1] = sPu[(m+8)*132 + k8 + tig];
                aF[i][2] = sPu[m*132 + k8 + 4 + tig];
                aF[i][3] = sPu[(m+8)*132 + k8 + 4 + tig];
            }
            #pragma unroll
            for (int i = 0; i < 2; i++)
                #pragma unroll
                for (int j = 0; j < 4; j++)
                    MMA_TF32R(oacc[i][j], aF[i], bF[j]);
        }
    }

    float* Ob = Og + (size_t)(b*1024 + qt*128) * 1024 + hh*64;
    #pragma unroll
    for (int i = 0; i < 2; i++)
        #pragma unroll
        for (int h2 = 0; h2 < 2; h2++) {
            int row = wm*32 + i*16 + grp + h2*8;
            float inv = 1.0f / l_i[i][h2];
            #pragma unroll
            for (int j = 0; j < 4; j++) {
                int col = wn*32 + j*8 + 2*tig;
                *(float2*)(Ob + (size_t)row*1024 + col) =
                    make_float2(rtf(oacc[i][j][h2*2]*inv), rtf(oacc[i][j][h2*2+1]*inv));
            }
        }
}

// ---------------- elementwise / small kernels ----------------
// Writes rounded output O (GEMM operand) and, if Of != nullptr, full-precision Of.
__global__ __launch_bounds__(256)
void k_rmsnorm(const float* __restrict__ X, const float* __restrict__ G,
               float* __restrict__ O, float* __restrict__ Of)
{
    int n = blockIdx.x;
    const float4* x4 = (const float4*)(X + (size_t)n * CDIM);
    const float4* g4 = (const float4*)G;
    float4 v = x4[threadIdx.x];
    float ss = v.x*v.x + v.y*v.y + v.z*v.z + v.w*v.w;
    float tot = block_reduce_sum256(ss);
    float r = 1.0f / sqrtf(tot * (1.0f / CDIM) + 1e-6f);
    float4 g = g4[threadIdx.x];
    float4 full = make_float4(v.x*r*g.x, v.y*r*g.y, v.z*r*g.z, v.w*r*g.w);
    if (Of) ((float4*)(Of + (size_t)n * CDIM))[threadIdx.x] = full;
    ((float4*)(O + (size_t)n * CDIM))[threadIdx.x] =
        make_float4(rtf(full.x), rtf(full.y), rtf(full.z), rtf(full.w));
}

__global__ __launch_bounds__(128)
void k_router(const float* __restrict__ HN, const float* __restrict__ WR,
              const float* __restrict__ RB)
{
    int n = blockIdx.x * 4 + (threadIdx.x >> 5);
    int lane = threadIdx.x & 31;
    const float* x = HN + (size_t)n * CDIM;
    float p[NEXP] = {};
    for (int c = lane; c < CDIM; c += 32) {
        float xv = x[c];
        #pragma unroll
        for (int e = 0; e < NEXP; e++) p[e] += xv * WR[c * NEXP + e];
    }
    #pragma unroll
    for (int e = 0; e < NEXP; e++) {
        #pragma unroll
        for (int o = 16; o; o >>= 1)
            p[e] += __shfl_xor_sync(0xffffffffu, p[e], o);
    }
    if (lane == 0) {
        float logit[NEXP], biased[NEXP];
        #pragma unroll
        for (int e = 0; e < NEXP; e++) {
            logit[e]  = p[e] * 0.03125f;
            biased[e] = logit[e] + RB[e];
        }
        int i0 = 0;
        #pragma unroll
        for (int e = 1; e < NEXP; e++) if (biased[e] > biased[i0]) i0 = e;
        int i1 = -1;
        #pragma unroll
        for (int e = 0; e < NEXP; e++) {
            if (e == i0) continue;
            if (i1 < 0 || biased[e] > biased[i1]) i1 = e;
        }
        float m  = fmaxf(logit[i0], logit[i1]);
        float e0 = expf(logit[i0] - m), e1 = expf(logit[i1] - m);
        float inv = 1.0f / (e0 + e1);
        g_top [n*2]     = i0; g_top [n*2 + 1] = i1;
        g_topw[n*2]     = e0 * inv;
        g_topw[n*2 + 1] = e1 * inv;
    }
}

__global__ __launch_bounds__(256)
void k_place()
{
    __shared__ int cnt[NEXP], offp[NEXP], cntp[NEXP], cur[NEXP];
    int tid = threadIdx.x;
    if (tid < NEXP) cnt[tid] = 0;
    __syncthreads();
    for (int i = tid; i < NTOK * 2; i += 256) atomicAdd(&cnt[g_top[i]], 1);
    __syncthreads();
    if (tid == 0) {
        int o = 0;
        for (int e = 0; e < NEXP; e++) {
            offp[e] = o;
            cntp[e] = ((cnt[e] + 127) >> 7) << 7;
            cur[e]  = o;
            g_off_pad[e] = o;
            g_cnt_pad[e] = cntp[e];
            o += cntp[e];
        }
    }
    __syncthreads();
    for (int i = tid; i < NTOK * 2; i += 256) {
        int e = g_top[i];
        int s = atomicAdd(&cur[e], 1);
        g_tok_of_slot[s] = i >> 1;
        g_w_of_slot[s]   = g_topw[i];
        g_slot_of_tok[i] = s;
    }
    __syncthreads();
    for (int e = 0; e < NEXP; e++) {
        int start = offp[e] + cnt[e];
        int end   = offp[e] + cntp[e];
        for (int i = start + tid; i < end; i += 256) {
            g_tok_of_slot[i] = 0;
            g_w_of_slot[i]   = 0.0f;
        }
    }
}

__global__ __launch_bounds__(256)
void k_combine(const float* __restrict__ SOUT, const float* __restrict__ CT,
               float* __restrict__ OUT)
{
    int n = blockIdx.x;
    int s0 = g_slot_of_tok[n*2], s1 = g_slot_of_tok[n*2 + 1];
    const float4* a  = (const float4*)(SOUT + (size_t)n  * CDIM);
    const float4* c0 = (const float4*)(CT   + (size_t)s0 * CDIM);
    const float4* c1 = (const float4*)(CT   + (size_t)s1 * CDIM);
    float4* o = (float4*)(OUT + (size_t)n * CDIM);
    int i = threadIdx.x;
    float4 va = a[i], v0 = c0[i], v1 = c1[i];
    o[i] = make_float4(va.x + v0.x + v1.x, va.y + v0.y + v1.y,
                       va.z + v0.z + v1.z, va.w + v0.w + v1.w);
}

// ---------------- launch ----------------
#define SM128  56832   // 3*(128*20*4) + 3*(16*136*4)
#define SM64   44544   // 3*(128*20*4) + 3*(16*72*4)
#define SM64D  58368   // 3*(128*20*4) + 2*3*(16*72*4)

extern "C" void kernel_launch(void* const* d_in, const int* in_sizes, int n_in,
                              void* d_out, int out_size)
{
    const float* x    = (const float*)d_in[0];
    const float* ga   = (const float*)d_in[1];
    const float* wq   = (const float*)d_in[2];
    const float* wkvd = (const float*)d_in[3];
    const float* wku  = (const float*)d_in[4];
    const float* wvu  = (const float*)d_in[5];
    const float* wo   = (const float*)d_in[6];
    const float* gm   = (const float*)d_in[7];
    const float* wr   = (const float*)d_in[8];
    const float* rb   = (const float*)d_in[9];
    const float* ew1  = (const float*)d_in[10];
    const float* ew2  = (const float*)d_in[11];
    const float* ew3  = (const float*)d_in[12];
    const float* sw1  = (const float*)d_in[13];
    const float* sw2  = (const float*)d_in[14];
    const float* sw3  = (const float*)d_in[15];
    float* out = (float*)d_out;

    float *xn, *q, *kv, *kvo, *att, *hb, *hn, *hnf, *hid, *ctb, *shid, *sout;
    float *wqkv_r, *wkv_r, *wo_r, *sw1_r, *sw3_r, *sw2_r, *ew1_r, *ew2_r, *ew3_r;
    cudaGetSymbolAddress((void**)&xn,   g_xn);
    cudaGetSymbolAddress((void**)&q,    g_q);
    cudaGetSymbolAddress((void**)&kv,   g_kv);
    cudaGetSymbolAddress((void**)&kvo,  g_kvo);
    cudaGetSymbolAddress((void**)&att,  g_att);
    cudaGetSymbolAddress((void**)&hb,   g_h);
    cudaGetSymbolAddress((void**)&hn,   g_hn);
    cudaGetSymbolAddress((void**)&hnf,  g_hnf);
    cudaGetSymbolAddress((void**)&hid,  g_hid);
    cudaGetSymbolAddress((void**)&ctb,  g_ctb);
    cudaGetSymbolAddress((void**)&shid, g_shid);
    cudaGetSymbolAddress((void**)&sout, g_sout);
    cudaGetSymbolAddress((void**)&wqkv_r, g_wqkv_r);
    cudaGetSymbolAddress((void**)&wkv_r,  g_wkv_r);
    cudaGetSymbolAddress((void**)&wo_r,   g_wo_r);
    cudaGetSymbolAddress((void**)&sw1_r,  g_sw1_r);
    cudaGetSymbolAddress((void**)&sw3_r,  g_sw3_r);
    cudaGetSymbolAddress((void**)&sw2_r,  g_sw2_r);
    cudaGetSymbolAddress((void**)&ew1_r,  g_ew1_r);
    cudaGetSymbolAddress((void**)&ew2_r,  g_ew2_r);
    cudaGetSymbolAddress((void**)&ew3_r,  g_ew3_r);

    cudaFuncSetAttribute(k_flash, cudaFuncAttributeMaxDynamicSharedMemorySize, FA_BYTES);
    cudaFuncSetAttribute(gemm_cp<M_QKV,128>,     cudaFuncAttributeMaxDynamicSharedMemorySize, SM128);
    cudaFuncSetAttribute(gemm_cp<M_PLAIN,64>,    cudaFuncAttributeMaxDynamicSharedMemorySize, SM64);
    cudaFuncSetAttribute(gemm_cp<M_RESID,128>,   cudaFuncAttributeMaxDynamicSharedMemorySize, SM128);
    cudaFuncSetAttribute(gemm_cp<M_DUAL,64>,     cudaFuncAttributeMaxDynamicSharedMemorySize, SM64D);
    cudaFuncSetAttribute(gemm_cp<M_EXPDUAL,64>,  cudaFuncAttributeMaxDynamicSharedMemorySize, SM64D);
    cudaFuncSetAttribute(gemm_cp<M_EXPDOWN,128>, cudaFuncAttributeMaxDynamicSharedMemorySize, SM128);

    // ---- tf32-round weights ----
    k_round_str<<<1024, 256>>>(wq,   1024, wqkv_r,        1536, 1024, 256);
    k_round_str<<<512,  256>>>(wkvd, 512,  wqkv_r + 1024, 1536, 1024, 128);
    k_round_str<<<32,   256>>>(wku,  64,   wkv_r,         128,  512,  16);
    k_round_str<<<32,   256>>>(wvu,  64,   wkv_r + 64,    128,  512,  16);
    k_round4<<<1024, 256>>>(wo,  wo_r,  CDIM*CDIM/4);
    k_round4<<<1024, 256>>>(sw1, sw1_r, CDIM*FSH/4);
    k_round4<<<1024, 256>>>(sw3, sw3_r, CDIM*FSH/4);
    k_round4<<<1024, 256>>>(sw2, sw2_r, FSH*CDIM/4);
    k_round4<<<2048, 256>>>(ew1, ew1_r, NEXP*CDIM*FDIM/4);
    k_round4<<<2048, 256>>>(ew2, ew2_r, NEXP*FDIM*CDIM/4);
    k_round4<<<2048, 256>>>(ew3, ew3_r, NEXP*CDIM*FDIM/4);

    // ---- attention ----
    k_rmsnorm<<<NTOK, 256>>>(x, ga, xn, nullptr);
    gemm_cp<M_QKV,128><<<dim3(12, 32), 256, SM128>>>(xn, 1024, wqkv_r, nullptr, 1536, nullptr, 0, nullptr, 1024);
    gemm_cp<M_PLAIN,64><<<dim3(2, 32), 256, SM64>>>(kv, 512, wkv_r, nullptr, 128, kvo, 128, nullptr, 512);
    k_flash<<<dim3(8, 64), 256, FA_BYTES>>>(q, kvo, att);
    gemm_cp<M_RESID,128><<<dim3(8, 32), 256, SM128>>>(att, 1024, wo_r, nullptr, 1024, hb, 1024, x, 1024);

    // ---- MoE ----
    k_rmsnorm<<<NTOK, 256>>>(hb, gm, hn, hnf);       // hn: rounded (GEMMs), hnf: full (router)
    k_router<<<NTOK/4, 128>>>(hnf, wr, rb);
    k_place<<<1, 256>>>();
    gemm_cp<M_EXPDUAL,64><<<dim3(16, 72, NEXP), 256, SM64D>>>(nullptr, 0, ew1_r, ew3_r, 1024, hid, 1024, nullptr, 1024);
    gemm_cp<M_EXPDOWN,128><<<dim3(8, 72, NEXP), 256, SM128>>>(nullptr, 0, ew2_r, nullptr, 1024, nullptr, 1024, nullptr, 1024);
    gemm_cp<M_DUAL,64><<<dim3(32, 32), 256, SM64D>>>(hn, 1024, sw1_r, sw3_r, 2048, shid, 2048, nullptr, 1024);
    gemm_cp<M_RESID,128><<<dim3(8, 32), 256, SM128>>>(shid, 2048, sw2_r, nullptr, 1024, sout, 1024, hb, 2048);
    k_combine<<<NTOK, 256>>>(sout, ctb, out);
}

// round 8
// speedup vs baseline: 4.0940x; 1.3746x over previous
#include <cuda_runtime.h>
#include <cuda_fp16.h>
#include <math.h>
#include <stdint.h>

// ---------------- problem dims ----------------
#define NTOK 4096
#define CDIM 1024
#define HD 64
#define LAT 512
#define NEXP 8
#define FDIM 1024
#define FSH 2048
#define MAXSLOT 9216

// ---------------- scratch ----------------
__device__ float g_xn [NTOK*CDIM];
__device__ float g_q  [NTOK*CDIM];
__device__ float g_kv [NTOK*LAT];
__device__ float g_kvo[NTOK*128];          // K|V interleaved per row
__device__ float g_att[NTOK*CDIM];
__device__ float g_h  [NTOK*CDIM];
__device__ float g_hnf[NTOK*CDIM];         // full fp32 (router only)
__device__ __half g_hn_h [NTOK*CDIM];      // half (MoE GEMM operand)
__device__ int   g_top[NTOK*2];
__device__ float g_topw[NTOK*2];
__device__ int   g_tok_of_slot[MAXSLOT];
__device__ float g_w_of_slot[MAXSLOT];
__device__ int   g_slot_of_tok[NTOK*2];
__device__ int   g_off_pad[NEXP];
__device__ int   g_cnt_pad[NEXP];
__device__ __half g_hid_h [MAXSLOT*FDIM];
__device__ float  g_ctb   [MAXSLOT*CDIM];
__device__ __half g_shid_h[NTOK*FSH];
__device__ float  g_sout  [NTOK*CDIM];

// attention weights: tf32-rounded fp32 (unchanged path)
__device__ float g_wqkv_r[CDIM*1536];
__device__ float g_wkv_r [LAT*128];
__device__ float g_wo_r  [CDIM*CDIM];
// MoE weights: half, transposed to [N][K]
__device__ __half g_sw1_h[FSH*CDIM];
__device__ __half g_sw3_h[FSH*CDIM];
__device__ __half g_sw2_h[CDIM*FSH];
__device__ __half g_ew1_h[NEXP*FDIM*CDIM];
__device__ __half g_ew3_h[NEXP*FDIM*CDIM];
__device__ __half g_ew2_h[NEXP*CDIM*FDIM];

// ---------------- helpers ----------------
__device__ __forceinline__ float siluf(float x) { return x / (1.0f + expf(-x)); }

__device__ __forceinline__ unsigned f2tf(float f) {
    unsigned u; asm("cvt.rna.tf32.f32 %0, %1;" : "=r"(u) : "f"(f)); return u;
}
__device__ __forceinline__ float rtf(float f) { return __uint_as_float(f2tf(f)); }

__device__ __forceinline__ uint32_t smem_u32(const void* p) {
    uint32_t a;
    asm("{ .reg .u64 t; cvta.to.shared.u64 t, %1; cvt.u32.u64 %0, t; }" : "=r"(a) : "l"(p));
    return a;
}
__device__ __forceinline__ void cpa16(uint32_t saddr, const void* g) {
    asm volatile("cp.async.cg.shared.global [%0], [%1], 16;" :: "r"(saddr), "l"(g));
}
#define CP_COMMIT() asm volatile("cp.async.commit_group;" ::: "memory")
#define CP_WAIT1()  asm volatile("cp.async.wait_group 1;" ::: "memory")

#define MMA_TF32R(d, a, b) asm volatile( \
  "mma.sync.aligned.m16n8k8.row.col.f32.tf32.tf32.f32 " \
  "{%0,%1,%2,%3}, {%4,%5,%6,%7}, {%8,%9}, {%0,%1,%2,%3};" \
  : "+f"(d[0]), "+f"(d[1]), "+f"(d[2]), "+f"(d[3]) \
  : "r"(a[0]), "r"(a[1]), "r"(a[2]), "r"(a[3]), "r"(b[0]), "r"(b[1]))

#define MMA_F16(d, a, b) asm volatile( \
  "mma.sync.aligned.m16n8k16.row.col.f32.f16.f16.f32 " \
  "{%0,%1,%2,%3}, {%4,%5,%6,%7}, {%8,%9}, {%0,%1,%2,%3};" \
  : "+f"(d[0]), "+f"(d[1]), "+f"(d[2]), "+f"(d[3]) \
  : "r"(a[0]), "r"(a[1]), "r"(a[2]), "r"(a[3]), "r"(b[0]), "r"(b[1]))

__device__ __forceinline__ float block_reduce_sum256(float v) {
    __shared__ float sm[8];
    __syncthreads();
    int lane = threadIdx.x & 31, w = threadIdx.x >> 5;
    #pragma unroll
    for (int o = 16; o; o >>= 1) v += __shfl_xor_sync(0xffffffffu, v, o);
    if (lane == 0) sm[w] = v;
    __syncthreads();
    float r = (threadIdx.x < 8) ? sm[threadIdx.x] : 0.0f;
    if (w == 0) {
        #pragma unroll
        for (int o = 4; o; o >>= 1) r += __shfl_xor_sync(0xffffffffu, r, o);
        if (lane == 0) sm[0] = r;
    }
    __syncthreads();
    return sm[0];
}

// ---------------- weight prep ----------------
__global__ __launch_bounds__(256)
void k_round4(const float* __restrict__ s, float* __restrict__ d, int n4)
{
    int i = blockIdx.x * 256 + threadIdx.x;
    int st = gridDim.x * 256;
    for (; i < n4; i += st) {
        float4 v = ((const float4*)s)[i];
        ((float4*)d)[i] = make_float4(rtf(v.x), rtf(v.y), rtf(v.z), rtf(v.w));
    }
}
__global__ __launch_bounds__(256)
void k_round_str(const float* __restrict__ s, int sld,
                 float* __restrict__ d, int dld, int rows, int cols4)
{
    int i = blockIdx.x * 256 + threadIdx.x;
    int st = gridDim.x * 256;
    int n = rows * cols4;
    for (; i < n; i += st) {
        int r = i / cols4, c = i % cols4;
        float4 v = *(const float4*)(s + (size_t)r * sld + c * 4);
        *(float4*)(d + (size_t)r * dld + c * 4) =
            make_float4(rtf(v.x), rtf(v.y), rtf(v.z), rtf(v.w));
    }
}
// src [R][C] fp32 (batched by z) -> dst [C][R] half
__global__ __launch_bounds__(256)
void k_cvt_tr(const float* __restrict__ S, __half* __restrict__ D, int R, int C)
{
    __shared__ float t[32][33];
    size_t so = (size_t)blockIdx.z * R * C;
    int c0 = blockIdx.x * 32, r0 = blockIdx.y * 32;
    int tx = threadIdx.x & 31, ty = threadIdx.x >> 5;
    #pragma unroll
    for (int i = 0; i < 4; i++)
        t[ty + i*8][tx] = S[so + (size_t)(r0 + ty + i*8) * C + c0 + tx];
    __syncthreads();
    #pragma unroll
    for (int i = 0; i < 4; i++)
        D[so + (size_t)(c0 + ty + i*8) * R + r0 + tx] = __float2half_rn(t[tx][ty + i*8]);
}

// ---------------- tf32 cp.async GEMM (attention path, unchanged math) ----------------
enum { M_PLAIN = 0, M_RESID = 1, M_QKV = 5 };

template<int MODE, int BN>
__global__ __launch_bounds__(256)
void gemm_cp(const float* __restrict__ Aa, int lda,
             const float* __restrict__ B1a, int ldb,
             float* __restrict__ Ca, int ldc,
             const float* __restrict__ Da, int K)
{
    constexpr int NT  = BN / 16;
    constexpr int SBS = BN + 8;
    constexpr int NCH = BN / 4;
    constexpr int TB  = BN / 64;
    extern __shared__ float dsm[];
    float* sA  = dsm;
    float* sB1 = dsm + 3 * 128 * 20;

    const int tid = threadIdx.x;
    const int nb = blockIdx.x, mb = blockIdx.y;
    const int m0 = mb * 128, n0 = nb * BN;

    const float* A = Aa; const float* B1 = B1a; float* C = Ca;
    int ldcx = ldc;

    const int lane = tid & 31, warp = tid >> 5;
    const int wm = warp & 3, wn = warp >> 2;
    const int mw = wm * 32, nw = wn * (BN / 2);
    const int grp = lane >> 2, tig = lane & 3;

    const int aRow0 = tid >> 2, aKc = tid & 3;
    const int KT = K >> 4;

    auto ISSUE = [&](int kt, int st) {
        if (kt < KT) {
            int k0 = kt << 4;
            #pragma unroll
            for (int t = 0; t < 2; t++) {
                int row = aRow0 + t * 64;
                cpa16(smem_u32(&sA[st * 128 * 20 + row * 20 + aKc * 4]),
                      A + (size_t)(m0 + row) * lda + k0 + aKc * 4);
            }
            #pragma unroll
            for (int t = 0; t < TB; t++) {
                int c = tid + 256 * t;
                int krow = c / NCH, nc = c % NCH;
                cpa16(smem_u32(&sB1[st * 16 * SBS + krow * SBS + nc * 4]),
                      B1 + (size_t)(k0 + krow) * ldb + n0 + nc * 4);
            }
        }
        CP_COMMIT();
    };

    float acc1[2][NT][4] = {};

    auto COMP = [&](int st) {
        const unsigned* uA  = (const unsigned*)(sA  + st * 128 * 20);
        const unsigned* uB1 = (const unsigned*)(sB1 + st * 16 * SBS);
        #pragma unroll
        for (int k8 = 0; k8 < 16; k8 += 8) {
            unsigned bF1[NT][2], aF[2][4];
            #pragma unroll
            for (int j = 0; j < NT; j++) {
                int n = nw + j * 8 + grp;
                bF1[j][0] = uB1[(k8 + tig) * SBS + n];
                bF1[j][1] = uB1[(k8 + 4 + tig) * SBS + n];
            }
            #pragma unroll
            for (int i = 0; i < 2; i++) {
                int m = mw + i * 16 + grp;
                aF[i][0] = uA[m * 20 + k8 + tig];
                aF[i][1] = uA[(m + 8) * 20 + k8 + tig];
                aF[i][2] = uA[m * 20 + k8 + 4 + tig];
                aF[i][3] = uA[(m + 8) * 20 + k8 + 4 + tig];
            }
            #pragma unroll
            for (int i = 0; i < 2; i++)
                #pragma unroll
                for (int j = 0; j < NT; j++)
                    MMA_TF32R(acc1[i][j], aF[i], bF1[j]);
        }
    };

    ISSUE(0, 0);
    ISSUE(1, 1);
    for (int kt = 0; kt < KT; kt++) {
        int st = kt % 3;
        CP_WAIT1();
        __syncthreads();
        ISSUE(kt + 2, (kt + 2) % 3);
        COMP(st);
    }

    #pragma unroll
    for (int i = 0; i < 2; i++) {
        #pragma unroll
        for (int j = 0; j < NT; j++) {
            #pragma unroll
            for (int hh = 0; hh < 2; hh++) {
                int ml = mw + i * 16 + grp + hh * 8;
                int nl = nw + j * 8 + 2 * tig;
                float v0 = acc1[i][j][hh * 2 + 0];
                float v1 = acc1[i][j][hh * 2 + 1];
                int gm = m0 + ml, gn = n0 + nl;
                if (MODE == M_QKV) {
                    v0 = rtf(v0); v1 = rtf(v1);
                    if (gn < 1024)
                        *(float2*)(g_q + (size_t)gm * 1024 + gn) = make_float2(v0, v1);
                    else
                        *(float2*)(g_kv + (size_t)gm * 512 + gn - 1024) = make_float2(v0, v1);
                } else if (MODE == M_RESID) {
                    float2 d = *(const float2*)(Da + (size_t)gm * ldcx + gn);
                    *(float2*)(C + (size_t)gm * ldcx + gn) = make_float2(v0 + d.x, v1 + d.y);
                } else {
                    v0 = rtf(v0); v1 = rtf(v1);
                    *(float2*)(C + (size_t)gm * ldcx + gn) = make_float2(v0, v1);
                }
            }
        }
    }
}

// ---------------- fp16 cp.async GEMM (MoE path) ----------------
enum { HP_DUAL = 0, HP_EXPDUAL = 1, HP_EXPDOWN = 2, HP_RESID = 3 };
#define SMHP 61440

template<int MODE, int BN>
__global__ __launch_bounds__(256)
void gemm_hp(const __half* __restrict__ Aa, int lda,
             const __half* __restrict__ B1a, const __half* __restrict__ B3a,
             void* __restrict__ Cv, int ldc,
             const float* __restrict__ Da, int K)
{
    constexpr bool DUAL = (MODE == HP_DUAL || MODE == HP_EXPDUAL);
    constexpr int NT  = BN / 16;      // n8 tiles per warp (warp spans BN/2)
    constexpr int BCH = BN / 64;      // 16B B-chunks per thread per matrix
    extern __shared__ __half hsm[];
    __half* sA  = hsm;                       // 3 x [128][40]
    __half* sB1 = hsm + 3 * 128 * 40;        // 3 x [BN][40]
    __half* sB3 = sB1 + (DUAL ? 3 * BN * 40 : 0);

    const int tid = threadIdx.x;
    const int nb = blockIdx.x, mb = blockIdx.y, z = blockIdx.z;
    const int m0 = mb * 128, n0 = nb * BN;

    const __half* A = Aa; const __half* B1 = B1a; const __half* B3 = B3a;
    const float* wrow = nullptr; const int* ridx = nullptr;
    void* C = Cv; int ldcx = ldc;

    if (MODE == HP_EXPDUAL) {
        if (m0 >= g_cnt_pad[z]) return;
        int off = g_off_pad[z];
        ridx = g_tok_of_slot + off;
        A = g_hn_h; lda = CDIM;
        B1 = B1a + (size_t)z * FDIM * CDIM;
        B3 = B3a + (size_t)z * FDIM * CDIM;
        C = (void*)(g_hid_h + (size_t)off * FDIM); ldcx = FDIM;
    } else if (MODE == HP_EXPDOWN) {
        if (m0 >= g_cnt_pad[z]) return;
        int off = g_off_pad[z];
        A = g_hid_h + (size_t)off * FDIM; lda = FDIM;
        B1 = B1a + (size_t)z * CDIM * FDIM;
        C = (void*)(g_ctb + (size_t)off * CDIM); ldcx = CDIM;
        wrow = g_w_of_slot + off;
    }

    const int lane = tid & 31, warp = tid >> 5;
    const int wm = warp & 3, wn = warp >> 2;
    const int mw = wm * 32, nw = wn * (BN / 2);
    const int grp = lane >> 2, tig = lane & 3;

    const int KT = K >> 5;

    auto ISSUE = [&](int kt, int st) {
        if (kt < KT) {
            int k0 = kt << 5;
            #pragma unroll
            for (int t = 0; t < 2; t++) {
                int c = tid + 256 * t;
                int row = c >> 2, q = c & 3;
                int gr = (MODE == HP_EXPDUAL) ? ridx[m0 + row] : (m0 + row);
                cpa16(smem_u32(&sA[st * 128 * 40 + row * 40 + q * 8]),
                      A + (size_t)gr * lda + k0 + q * 8);
            }
            #pragma unroll
            for (int t = 0; t < BCH; t++) {
                int c = tid + 256 * t;
                int row = c >> 2, q = c & 3;
                cpa16(smem_u32(&sB1[st * BN * 40 + row * 40 + q * 8]),
                      B1 + (size_t)(n0 + row) * K + k0 + q * 8);
                if (DUAL)
                    cpa16(smem_u32(&sB3[st * BN * 40 + row * 40 + q * 8]),
                          B3 + (size_t)(n0 + row) * K + k0 + q * 8);
            }
        }
        CP_COMMIT();
    };

    float acc1[2][NT][4] = {};
    float acc3[2][DUAL ? NT : 1][4] = {};

    auto COMP = [&](int st) {
        const unsigned* uA  = (const unsigned*)(sA  + st * 128 * 40);
        const unsigned* uB1 = (const unsigned*)(sB1 + st * BN * 40);
        const unsigned* uB3 = (const unsigned*)(sB3 + st * BN * 40);
        #pragma unroll
        for (int s16 = 0; s16 < 2; s16++) {
            int ko = s16 * 8;   // uint units (16 halves)
            unsigned bF1[NT][2], bF3[DUAL ? NT : 1][2], aF[2][4];
            #pragma unroll
            for (int j = 0; j < NT; j++) {
                int n = nw + j * 8 + grp;
                bF1[j][0] = uB1[n * 20 + ko + tig];
                bF1[j][1] = uB1[n * 20 + ko + 4 + tig];
                if (DUAL) {
                    bF3[j][0] = uB3[n * 20 + ko + tig];
                    bF3[j][1] = uB3[n * 20 + ko + 4 + tig];
                }
            }
            #pragma unroll
            for (int i = 0; i < 2; i++) {
                int m = mw + i * 16 + grp;
                aF[i][0] = uA[m * 20 + ko + tig];
                aF[i][1] = uA[(m + 8) * 20 + ko + tig];
                aF[i][2] = uA[m * 20 + ko + 4 + tig];
                aF[i][3] = uA[(m + 8) * 20 + ko + 4 + tig];
            }
            #pragma unroll
            for (int i = 0; i < 2; i++)
                #pragma unroll
                for (int j = 0; j < NT; j++) {
                    MMA_F16(acc1[i][j], aF[i], bF1[j]);
                    if (DUAL) MMA_F16(acc3[i][j], aF[i], bF3[j]);
                }
        }
    };

    ISSUE(0, 0);
    ISSUE(1, 1);
    for (int kt = 0; kt < KT; kt++) {
        int st = kt % 3;
        CP_WAIT1();
        __syncthreads();
        ISSUE(kt + 2, (kt + 2) % 3);
        COMP(st);
    }

    #pragma unroll
    for (int i = 0; i < 2; i++) {
        #pragma unroll
        for (int j = 0; j < NT; j++) {
            #pragma unroll
            for (int hh = 0; hh < 2; hh++) {
                int ml = mw + i * 16 + grp + hh * 8;
                int nl = nw + j * 8 + 2 * tig;
                float v0 = acc1[i][j][hh * 2 + 0];
                float v1 = acc1[i][j][hh * 2 + 1];
                int gm = m0 + ml, gn = n0 + nl;
                if (DUAL) {
                    v0 = v0 * siluf(acc3[i][j][hh * 2 + 0]);
                    v1 = v1 * siluf(acc3[i][j][hh * 2 + 1]);
                    __half2 hv = __floats2half2_rn(v0, v1);
                    *(__half2*)((__half*)C + (size_t)gm * ldcx + gn) = hv;
                } else if (MODE == HP_EXPDOWN) {
                    float w = wrow[gm];
                    *(float2*)((float*)C + (size_t)gm * ldcx + gn) = make_float2(v0 * w, v1 * w);
                } else {  // HP_RESID
                    float2 d = *(const float2*)(Da + (size_t)gm * ldcx + gn);
                    *(float2*)((float*)C + (size_t)gm * ldcx + gn) = make_float2(v0 + d.x, v1 + d.y);
                }
            }
        }
    }
}

// ---------------- flash attention (tf32 mma, online softmax, unchanged) ----------------
#define FA_BYTES 173056

__global__ __launch_bounds__(256)
void k_flash(const float* __restrict__ Qg, const float* __restrict__ KVg,
             float* __restrict__ Og)
{
    extern __shared__ float fsm[];
    float* sQ  = fsm;            // [128][68]
    float* sKt = fsm + 8704;     // [64][132]
    float* sV  = fsm + 17152;    // [128][68]
    float* sP  = fsm + 25856;    // [128][132]
    float* sRM = fsm + 42752;
    float* sRS = fsm + 43008;
    unsigned* sQu  = (unsigned*)sQ;
    unsigned* sKtu = (unsigned*)sKt;
    unsigned* sVu  = (unsigned*)sV;
    unsigned* sPu  = (unsigned*)sP;

    const int qt = blockIdx.x, bh = blockIdx.y;
    const int b = bh >> 4, hh = bh & 15;
    const int tid = threadIdx.x, warp = tid >> 5, lane = tid & 31;
    const int wm = warp & 3, wn = warp >> 2;
    const int grp = lane >> 2, tig = lane & 3;
    const float NEG = -1e30f;

    const float* Qb = Qg + (size_t)(b*1024 + qt*128) * 1024 + hh*64;
    #pragma unroll
    for (int t = 0; t < 8; t++) {
        int idx = tid + t*256;
        int r = idx >> 4, dq = idx & 15;
        float4 v = *(const float4*)(Qb + (size_t)r*1024 + dq*4);
        unsigned* p = &sQu[r*68 + dq*4];
        p[0]=f2tf(v.x*0.125f); p[1]=f2tf(v.y*0.125f);
        p[2]=f2tf(v.z*0.125f); p[3]=f2tf(v.w*0.125f);
    }

    float m_i[2][2] = {{NEG,NEG},{NEG,NEG}};
    float l_i[2][2] = {{0.f,0.f},{0.f,0.f}};
    float oacc[2][4][4] = {};

    for (int kt = 0; kt <= qt; kt++) {
        __syncthreads();
        const float* KVb = KVg + (size_t)(b*1024 + kt*128) * 128;
        #pragma unroll
        for (int t = 0; t < 8; t++) {
            int idx = tid + t*256;
            int s = idx >> 4, dq = idx & 15;
            int d = dq*4;
            float4 k4 = *(const float4*)(KVb + (size_t)s*128 + d);
            sKtu[(d+0)*132 + s] = __float_as_uint(k4.x);
            sKtu[(d+1)*132 + s] = __float_as_uint(k4.y);
            sKtu[(d+2)*132 + s] = __float_as_uint(k4.z);
            sKtu[(d+3)*132 + s] = __float_as_uint(k4.w);
            float4 v4 = *(const float4*)(KVb + (size_t)s*128 + 64 + d);
            unsigned* p = &sVu[s*68 + d];
            p[0]=__float_as_uint(v4.x); p[1]=__float_as_uint(v4.y);
            p[2]=__float_as_uint(v4.z); p[3]=__float_as_uint(v4.w);
        }
        __syncthreads();

        float sacc[2][8][4] = {};
        #pragma unroll
        for (int k8 = 0; k8 < 64; k8 += 8) {
            unsigned aF[2][4], bF[8][2];
            #pragma unroll
            for (int j = 0; j < 8; j++) {
                int n = wn*64 + j*8 + grp;
                bF[j][0] = sKtu[(k8+tig)*132 + n];
                bF[j][1] = sKtu[(k8+4+tig)*132 + n];
            }
            #pragma unroll
            for (int i = 0; i < 2; i++) {
                int m = wm*32 + i*16 + grp;
                aF[i][0] = sQu[m*68 + k8 + tig];
                aF[i][1] = sQu[(m+8)*68 + k8 + tig];
                aF[i][2] = sQu[m*68 + k8 + 4 + tig];
                aF[i][3] = sQu[(m+8)*68 + k8 + 4 + tig];
            }
            #pragma unroll
            for (int i = 0; i < 2; i++)
                #pragma unroll
                for (int j = 0; j < 8; j++)
                    MMA_TF32R(sacc[i][j], aF[i], bF[j]);
        }

        if (kt == qt) {
            #pragma unroll
            for (int i = 0; i < 2; i++)
                #pragma unroll
                for (int h2 = 0; h2 < 2; h2++) {
                    int row = wm*32 + i*16 + grp + h2*8;
                    #pragma unroll
                    for (int j = 0; j < 8; j++) {
                        int col = wn*64 + j*8 + 2*tig;
                        if (col   > row) sacc[i][j][h2*2]   = NEG;
                        if (col+1 > row) sacc[i][j][h2*2+1] = NEG;
                    }
                }
        }

        #pragma unroll
        for (int i = 0; i < 2; i++)
            #pragma unroll
            for (int h2 = 0; h2 < 2; h2++) {
                float v = NEG;
                #pragma unroll
                for (int j = 0; j < 8; j++)
                    v = fmaxf(v, fmaxf(sacc[i][j][h2*2], sacc[i][j][h2*2+1]));
                v = fmaxf(v, __shfl_xor_sync(0xffffffffu, v, 1));
                v = fmaxf(v, __shfl_xor_sync(0xffffffffu, v, 2));
                if (tig == 0) sRM[wn*128 + wm*32 + i*16 + grp + h2*8] = v;
            }
        __syncthreads();

        #pragma unroll
        for (int i = 0; i < 2; i++)
            #pragma unroll
            for (int h2 = 0; h2 < 2; h2++) {
                int row = wm*32 + i*16 + grp + h2*8;
                float mnew = fmaxf(m_i[i][h2], fmaxf(sRM[row], sRM[128+row]));
                float fac = __expf(m_i[i][h2] - mnew);
                m_i[i][h2] = mnew;
                l_i[i][h2] *= fac;
                #pragma unroll
                for (int j = 0; j < 4; j++) {
                    oacc[i][j][h2*2]   *= fac;
                    oacc[i][j][h2*2+1] *= fac;
                }
                float rs = 0.0f;
                #pragma unroll
                for (int j = 0; j < 8; j++) {
                    float p0 = __expf(sacc[i][j][h2*2]   - mnew);
                    float p1 = __expf(sacc[i][j][h2*2+1] - mnew);
                    rs += p0 + p1;
                    int col = wn*64 + j*8 + 2*tig;
                    sPu[row*132 + col]     = f2tf(p0);
                    sPu[row*132 + col + 1] = f2tf(p1);
                }
                rs += __shfl_xor_sync(0xffffffffu, rs, 1);
                rs += __shfl_xor_sync(0xffffffffu, rs, 2);
                if (tig == 0) sRS[wn*128 + row] = rs;
            }
        __syncthreads();
        #pragma unroll
        for (int i = 0; i < 2; i++)
            #pragma unroll
            for (int h2 = 0; h2 < 2; h2++) {
                int row = wm*32 + i*16 + grp + h2*8;
                l_i[i][h2] += sRS[row] + sRS[128 + row];
            }

        #pragma unroll
        for (int k8 = 0; k8 < 128; k8 += 8) {
            unsigned aF[2][4], bF[4][2];
            #pragma unroll
            for (int j = 0; j < 4; j++) {
                int n = wn*32 + j*8 + grp;
                bF[j][0] = sVu[(k8+tig)*68 + n];
                bF[j][1] = sVu[(k8+4+tig)*68 + n];
            }
            #pragma unroll
            for (int i = 0; i < 2; i++) {
                int m = wm*32 + i*16 + grp;
                aF[i][0] = sPu[m*132 + k8 + tig];
                aF[i][1] = sPu[(m+8)*132 + k8 + tig];
                aF[i][2] = sPu[m*132 + k8 + 4 + tig];
                aF[i][3] = sPu[(m+8)*132 + k8 + 4 + tig];
            }
            #pragma unroll
            for (int i = 0; i < 2; i++)
                #pragma unroll
                for (int j = 0; j < 4; j++)
                    MMA_TF32R(oacc[i][j], aF[i], bF[j]);
        }
    }

    float* Ob = Og + (size_t)(b*1024 + qt*128) * 1024 + hh*64;
    #pragma unroll
    for (int i = 0; i < 2; i++)
        #pragma unroll
        for (int h2 = 0; h2 < 2; h2++) {
            int row = wm*32 + i*16 + grp + h2*8;
            float inv = 1.0f / l_i[i][h2];
            #pragma unroll
            for (int j = 0; j < 4; j++) {
                int col = wn*32 + j*8 + 2*tig;
                *(float2*)(Ob + (size_t)row*1024 + col) =
                    make_float2(rtf(oacc[i][j][h2*2]*inv), rtf(oacc[i][j][h2*2+1]*inv));
            }
        }
}

// ---------------- elementwise / small kernels ----------------
// O  : tf32-rounded fp32 output (nullable)
// Of : full fp32 output (nullable)
// Oh : half output (nullable)
__global__ __launch_bounds__(256)
void k_rmsnorm(const float* __restrict__ X, const float* __restrict__ G,
               float* __restrict__ O, float* __restrict__ Of, __half* __restrict__ Oh)
{
    int n = blockIdx.x;
    const float4* x4 = (const float4*)(X + (size_t)n * CDIM);
    const float4* g4 = (const float4*)G;
    float4 v = x4[threadIdx.x];
    float ss = v.x*v.x + v.y*v.y + v.z*v.z + v.w*v.w;
    float tot = block_reduce_sum256(ss);
    float r = 1.0f / sqrtf(tot * (1.0f / CDIM) + 1e-6f);
    float4 g = g4[threadIdx.x];
    float4 full = make_float4(v.x*r*g.x, v.y*r*g.y, v.z*r*g.z, v.w*r*g.w);
    if (Of) ((float4*)(Of + (size_t)n * CDIM))[threadIdx.x] = full;
    if (O)  ((float4*)(O + (size_t)n * CDIM))[threadIdx.x] =
        make_float4(rtf(full.x), rtf(full.y), rtf(full.z), rtf(full.w));
    if (Oh) {
        __half2 h0 = __floats2half2_rn(full.x, full.y);
        __half2 h1 = __floats2half2_rn(full.z, full.w);
        *(__half2*)(Oh + (size_t)n * CDIM + threadIdx.x * 4)     = h0;
        *(__half2*)(Oh + (size_t)n * CDIM + threadIdx.x * 4 + 2) = h1;
    }
}

__global__ __launch_bounds__(128)
void k_router(const float* __restrict__ HN, const float* __restrict__ WR,
              const float* __restrict__ RB)
{
    int n = blockIdx.x * 4 + (threadIdx.x >> 5);
    int lane = threadIdx.x & 31;
    const float* x = HN + (size_t)n * CDIM;
    float p[NEXP] = {};
    for (int c = lane; c < CDIM; c += 32) {
        float xv = x[c];
        #pragma unroll
        for (int e = 0; e < NEXP; e++) p[e] += xv * WR[c * NEXP + e];
    }
    #pragma unroll
    for (int e = 0; e < NEXP; e++) {
        #pragma unroll
        for (int o = 16; o; o >>= 1)
            p[e] += __shfl_xor_sync(0xffffffffu, p[e], o);
    }
    if (lane == 0) {
        float logit[NEXP], biased[NEXP];
        #pragma unroll
        for (int e = 0; e < NEXP; e++) {
            logit[e]  = p[e] * 0.03125f;
            biased[e] = logit[e] + RB[e];
        }
        int i0 = 0;
        #pragma unroll
        for (int e = 1; e < NEXP; e++) if (biased[e] > biased[i0]) i0 = e;
        int i1 = -1;
        #pragma unroll
        for (int e = 0; e < NEXP; e++) {
            if (e == i0) continue;
            if (i1 < 0 || biased[e] > biased[i1]) i1 = e;
        }
        float m  = fmaxf(logit[i0], logit[i1]);
        float e0 = expf(logit[i0] - m), e1 = expf(logit[i1] - m);
        float inv = 1.0f / (e0 + e1);
        g_top [n*2]     = i0; g_top [n*2 + 1] = i1;
        g_topw[n*2]     = e0 * inv;
        g_topw[n*2 + 1] = e1 * inv;
    }
}

__global__ __launch_bounds__(256)
void k_place()
{
    __shared__ int cnt[NEXP], offp[NEXP], cntp[NEXP], cur[NEXP];
    int tid = threadIdx.x;
    if (tid < NEXP) cnt[tid] = 0;
    __syncthreads();
    for (int i = tid; i < NTOK * 2; i += 256) atomicAdd(&cnt[g_top[i]], 1);
    __syncthreads();
    if (tid == 0) {
        int o = 0;
        for (int e = 0; e < NEXP; e++) {
            offp[e] = o;
            cntp[e] = ((cnt[e] + 127) >> 7) << 7;
            cur[e]  = o;
            g_off_pad[e] = o;
            g_cnt_pad[e] = cntp[e];
            o += cntp[e];
        }
    }
    __syncthreads();
    for (int i = tid; i < NTOK * 2; i += 256) {
        int e = g_top[i];
        int s = atomicAdd(&cur[e], 1);
        g_tok_of_slot[s] = i >> 1;
        g_w_of_slot[s]   = g_topw[i];
        g_slot_of_tok[i] = s;
    }
    __syncthreads();
    for (int e = 0; e < NEXP; e++) {
        int start = offp[e] + cnt[e];
        int end   = offp[e] + cntp[e];
        for (int i = start + tid; i < end; i += 256) {
            g_tok_of_slot[i] = 0;
            g_w_of_slot[i]   = 0.0f;
        }
    }
}

__global__ __launch_bounds__(256)
void k_combine(const float* __restrict__ SOUT, const float* __restrict__ CT,
               float* __restrict__ OUT)
{
    int n = blockIdx.x;
    int s0 = g_slot_of_tok[n*2], s1 = g_slot_of_tok[n*2 + 1];
    const float4* a  = (const float4*)(SOUT + (size_t)n  * CDIM);
    const float4* c0 = (const float4*)(CT   + (size_t)s0 * CDIM);
    const float4* c1 = (const float4*)(CT   + (size_t)s1 * CDIM);
    float4* o = (float4*)(OUT + (size_t)n * CDIM);
    int i = threadIdx.x;
    float4 va = a[i], v0 = c0[i], v1 = c1[i];
    o[i] = make_float4(va.x + v0.x + v1.x, va.y + v0.y + v1.y,
                       va.z + v0.z + v1.z, va.w + v0.w + v1.w);
}

// ---------------- launch ----------------
#define SM128  56832   // tf32: 3*(128*20*4) + 3*(16*136*4)
#define SM64   44544   // tf32: 3*(128*20*4) + 3*(16*72*4)

extern "C" void kernel_launch(void* const* d_in, const int* in_sizes, int n_in,
                              void* d_out, int out_size)
{
    const float* x    = (const float*)d_in[0];
    const float* ga   = (const float*)d_in[1];
    const float* wq   = (const float*)d_in[2];
    const float* wkvd = (const float*)d_in[3];
    const float* wku  = (const float*)d_in[4];
    const float* wvu  = (const float*)d_in[5];
    const float* wo   = (const float*)d_in[6];
    const float* gm   = (const float*)d_in[7];
    const float* wr   = (const float*)d_in[8];
    const float* rb   = (const float*)d_in[9];
    const float* ew1  = (const float*)d_in[10];
    const float* ew2  = (const float*)d_in[11];
    const float* ew3  = (const float*)d_in[12];
    const float* sw1  = (const float*)d_in[13];
    const float* sw2  = (const float*)d_in[14];
    const float* sw3  = (const float*)d_in[15];
    float* out = (float*)d_out;

    float *xn, *q, *kv, *kvo, *att, *hb, *hnf, *ctb, *sout;
    float *wqkv_r, *wkv_r, *wo_r;
    __half *hn_h, *hid_h, *shid_h, *sw1_h, *sw3_h, *sw2_h, *ew1_h, *ew2_h, *ew3_h;
    cudaGetSymbolAddress((void**)&xn,   g_xn);
    cudaGetSymbolAddress((void**)&q,    g_q);
    cudaGetSymbolAddress((void**)&kv,   g_kv);
    cudaGetSymbolAddress((void**)&kvo,  g_kvo);
    cudaGetSymbolAddress((void**)&att,  g_att);
    cudaGetSymbolAddress((void**)&hb,   g_h);
    cudaGetSymbolAddress((void**)&hnf,  g_hnf);
    cudaGetSymbolAddress((void**)&ctb,  g_ctb);
    cudaGetSymbolAddress((void**)&sout, g_sout);
    cudaGetSymbolAddress((void**)&wqkv_r, g_wqkv_r);
    cudaGetSymbolAddress((void**)&wkv_r,  g_wkv_r);
    cudaGetSymbolAddress((void**)&wo_r,   g_wo_r);
    cudaGetSymbolAddress((void**)&hn_h,   g_hn_h);
    cudaGetSymbolAddress((void**)&hid_h,  g_hid_h);
    cudaGetSymbolAddress((void**)&shid_h, g_shid_h);
    cudaGetSymbolAddress((void**)&sw1_h,  g_sw1_h);
    cudaGetSymbolAddress((void**)&sw3_h,  g_sw3_h);
    cudaGetSymbolAddress((void**)&sw2_h,  g_sw2_h);
    cudaGetSymbolAddress((void**)&ew1_h,  g_ew1_h);
    cudaGetSymbolAddress((void**)&ew2_h,  g_ew2_h);
    cudaGetSymbolAddress((void**)&ew3_h,  g_ew3_h);

    cudaFuncSetAttribute(k_flash, cudaFuncAttributeMaxDynamicSharedMemorySize, FA_BYTES);
    cudaFuncSetAttribute(gemm_cp<M_QKV,128>,   cudaFuncAttributeMaxDynamicSharedMemorySize, SM128);
    cudaFuncSetAttribute(gemm_cp<M_PLAIN,64>,  cudaFuncAttributeMaxDynamicSharedMemorySize, SM64);
    cudaFuncSetAttribute(gemm_cp<M_RESID,128>, cudaFuncAttributeMaxDynamicSharedMemorySize, SM128);
    cudaFuncSetAttribute(gemm_hp<HP_DUAL,64>,     cudaFuncAttributeMaxDynamicSharedMemorySize, SMHP);
    cudaFuncSetAttribute(gemm_hp<HP_EXPDUAL,64>,  cudaFuncAttributeMaxDynamicSharedMemorySize, SMHP);
    cudaFuncSetAttribute(gemm_hp<HP_EXPDOWN,128>, cudaFuncAttributeMaxDynamicSharedMemorySize, SMHP);
    cudaFuncSetAttribute(gemm_hp<HP_RESID,128>,   cudaFuncAttributeMaxDynamicSharedMemorySize, SMHP);

    // ---- attention weights: tf32-round (fp32) ----
    k_round_str<<<1024, 256>>>(wq,   1024, wqkv_r,        1536, 1024, 256);
    k_round_str<<<512,  256>>>(wkvd, 512,  wqkv_r + 1024, 1536, 1024, 128);
    k_round_str<<<32,   256>>>(wku,  64,   wkv_r,         128,  512,  16);
    k_round_str<<<32,   256>>>(wvu,  64,   wkv_r + 64,    128,  512,  16);
    k_round4<<<1024, 256>>>(wo, wo_r, CDIM*CDIM/4);

    // ---- MoE weights: convert + transpose to [N][K] half ----
    k_cvt_tr<<<dim3(32, 32, NEXP), 256>>>(ew1, ew1_h, CDIM, FDIM);
    k_cvt_tr<<<dim3(32, 32, NEXP), 256>>>(ew3, ew3_h, CDIM, FDIM);
    k_cvt_tr<<<dim3(32, 32, NEXP), 256>>>(ew2, ew2_h, FDIM, CDIM);
    k_cvt_tr<<<dim3(64, 32), 256>>>(sw1, sw1_h, CDIM, FSH);
    k_cvt_tr<<<dim3(64, 32), 256>>>(sw3, sw3_h, CDIM, FSH);
    k_cvt_tr<<<dim3(32, 64), 256>>>(sw2, sw2_h, FSH, CDIM);

    // ---- attention (tf32 path, bit-identical to R7) ----
    k_rmsnorm<<<NTOK, 256>>>(x, ga, xn, nullptr, nullptr);
    gemm_cp<M_QKV,128><<<dim3(12, 32), 256, SM128>>>(xn, 1024, wqkv_r, 1536, nullptr, 0, nullptr, 1024);
    gemm_cp<M_PLAIN,64><<<dim3(2, 32), 256, SM64>>>(kv, 512, wkv_r, 128, kvo, 128, nullptr, 512);
    k_flash<<<dim3(8, 64), 256, FA_BYTES>>>(q, kvo, att);
    gemm_cp<M_RESID,128><<<dim3(8, 32), 256, SM128>>>(att, 1024, wo_r, 1024, hb, 1024, x, 1024);

    // ---- MoE (fp16 GEMMs; routing input bit-identical to R7) ----
    k_rmsnorm<<<NTOK, 256>>>(hb, gm, nullptr, hnf, hn_h);
    k_router<<<NTOK/4, 128>>>(hnf, wr, rb);
    k_place<<<1, 256>>>();
    gemm_hp<HP_EXPDUAL,64><<<dim3(16, 72, NEXP), 256, SMHP>>>(nullptr, 0, ew1_h, ew3_h, nullptr, 0, nullptr, 1024);
    gemm_hp<HP_EXPDOWN,128><<<dim3(8, 72, NEXP), 256, SMHP>>>(nullptr, 0, ew2_h, nullptr, nullptr, 0, nullptr, 1024);
    gemm_hp<HP_DUAL,64><<<dim3(32, 32), 256, SMHP>>>(hn_h, 1024, sw1_h, sw3_h, shid_h, 2048, nullptr, 1024);
    gemm_hp<HP_RESID,128><<<dim3(8, 32), 256, SMHP>>>(shid_h, 2048, sw2_h, nullptr, sout, 1024, hb, 2048);
    k_combine<<<NTOK, 256>>>(sout, ctb, out);
}

// round 10
// speedup vs baseline: 4.7547x; 1.1614x over previous
#include <cuda_runtime.h>
#include <cuda_fp16.h>
#include <math.h>
#include <stdint.h>
#include <string.h>

// ---------------- problem dims ----------------
#define NTOK 4096
#define CDIM 1024
#define HD 64
#define LAT 512
#define NEXP 8
#define FDIM 1024
#define FSH 2048
#define MAXSLOT 9216

// ---------------- scratch ----------------
__device__ __half g_xn_h [NTOK*CDIM];
__device__ __half g_q_h  [NTOK*CDIM];      // pre-scaled by 0.125
__device__ __half g_kv_h [NTOK*LAT];
__device__ __half g_kvo_h[NTOK*128];       // K|V interleaved per row
__device__ __half g_att_h[NTOK*CDIM];
__device__ float  g_h    [NTOK*CDIM];
__device__ float  g_hnf  [NTOK*CDIM];      // full fp32 (router only)
__device__ __half g_hn_h [NTOK*CDIM];      // half (MoE GEMM operand)
__device__ int    g_top[NTOK*2];
__device__ float  g_topw[NTOK*2];
__device__ int    g_tok_of_slot[MAXSLOT];
__device__ float  g_w_of_slot[MAXSLOT];
__device__ int    g_slot_of_tok[NTOK*2];
__device__ int    g_off_pad[NEXP];
__device__ int    g_cnt_pad[NEXP];
__device__ __half g_hid_h [MAXSLOT*FDIM];
__device__ float  g_ctb   [MAXSLOT*CDIM];
__device__ __half g_shid_h[NTOK*FSH];
__device__ float  g_sout  [NTOK*CDIM];

// half weights, transposed to [N][K]
__device__ __half g_wqkv_h[1536*CDIM];
__device__ __half g_wkv_h [128*LAT];
__device__ __half g_wo_h  [CDIM*CDIM];
__device__ __half g_sw1_h[FSH*CDIM];
__device__ __half g_sw3_h[FSH*CDIM];
__device__ __half g_sw2_h[CDIM*FSH];
__device__ __half g_ew1_h[NEXP*FDIM*CDIM];
__device__ __half g_ew3_h[NEXP*FDIM*CDIM];
__device__ __half g_ew2_h[NEXP*CDIM*FDIM];

// ---------------- helpers ----------------
__device__ __forceinline__ float siluf(float x) { return x / (1.0f + expf(-x)); }

__device__ __forceinline__ unsigned h2_as_u32(__half2 h) {
    unsigned u;
    memcpy(&u, &h, 4);
    return u;
}

__device__ __forceinline__ uint32_t smem_u32(const void* p) {
    uint32_t a;
    asm("{ .reg .u64 t; cvta.to.shared.u64 t, %1; cvt.u32.u64 %0, t; }" : "=r"(a) : "l"(p));
    return a;
}
__device__ __forceinline__ void cpa16(uint32_t saddr, const void* g) {
    asm volatile("cp.async.cg.shared.global [%0], [%1], 16;" :: "r"(saddr), "l"(g));
}
#define CP_COMMIT() asm volatile("cp.async.commit_group;" ::: "memory")
#define CP_WAIT1()  asm volatile("cp.async.wait_group 1;" ::: "memory")

#define MMA_F16(d, a, b) asm volatile( \
  "mma.sync.aligned.m16n8k16.row.col.f32.f16.f16.f32 " \
  "{%0,%1,%2,%3}, {%4,%5,%6,%7}, {%8,%9}, {%0,%1,%2,%3};" \
  : "+f"(d[0]), "+f"(d[1]), "+f"(d[2]), "+f"(d[3]) \
  : "r"(a[0]), "r"(a[1]), "r"(a[2]), "r"(a[3]), "r"(b[0]), "r"(b[1]))

__device__ __forceinline__ float block_reduce_sum256(float v) {
    __shared__ float sm[8];
    __syncthreads();
    int lane = threadIdx.x & 31, w = threadIdx.x >> 5;
    #pragma unroll
    for (int o = 16; o; o >>= 1) v += __shfl_xor_sync(0xffffffffu, v, o);
    if (lane == 0) sm[w] = v;
    __syncthreads();
    float r = (threadIdx.x < 8) ? sm[threadIdx.x] : 0.0f;
    if (w == 0) {
        #pragma unroll
        for (int o = 4; o; o >>= 1) r += __shfl_xor_sync(0xffffffffu, r, o);
        if (lane == 0) sm[0] = r;
    }
    __syncthreads();
    return sm[0];
}

// ---------------- weight prep: src [R][C] fp32 (batched by z) -> dst [C][R] half --
__global__ __launch_bounds__(256)
void k_cvt_tr(const float* __restrict__ S, __half* __restrict__ D, int R, int C)
{
    __shared__ float t[32][33];
    size_t so = (size_t)blockIdx.z * R * C;
    int c0 = blockIdx.x * 32, r0 = blockIdx.y * 32;
    int tx = threadIdx.x & 31, ty = threadIdx.x >> 5;
    #pragma unroll
    for (int i = 0; i < 4; i++)
        t[ty + i*8][tx] = S[so + (size_t)(r0 + ty + i*8) * C + c0 + tx];
    __syncthreads();
    #pragma unroll
    for (int i = 0; i < 4; i++)
        D[so + (size_t)(c0 + ty + i*8) * R + r0 + tx] = __float2half_rn(t[tx][ty + i*8]);
}

// ---------------- fp16 cp.async GEMM ----------------
enum { HP_DUAL = 0, HP_EXPDUAL = 1, HP_EXPDOWN = 2, HP_RESID = 3, HP_QKV = 4, HP_HALF = 5 };
#define SMHP 61440

template<int MODE, int BN>
__global__ __launch_bounds__(256)
void gemm_hp(const __half* __restrict__ Aa, int lda,
             const __half* __restrict__ B1a, const __half* __restrict__ B3a,
             void* __restrict__ Cv, int ldc,
             const float* __restrict__ Da, int K)
{
    constexpr bool DUAL = (MODE == HP_DUAL || MODE == HP_EXPDUAL);
    constexpr int NT  = BN / 16;
    constexpr int BCH = BN / 64;
    extern __shared__ __half hsm[];
    __half* sA  = hsm;                       // 3 x [128][40]
    __half* sB1 = hsm + 3 * 128 * 40;        // 3 x [BN][40]
    __half* sB3 = sB1 + (DUAL ? 3 * BN * 40 : 0);

    const int tid = threadIdx.x;
    const int nb = blockIdx.x, mb = blockIdx.y, z = blockIdx.z;
    const int m0 = mb * 128, n0 = nb * BN;

    const __half* A = Aa; const __half* B1 = B1a; const __half* B3 = B3a;
    const float* wrow = nullptr; const int* ridx = nullptr;
    void* C = Cv; int ldcx = ldc;

    if (MODE == HP_EXPDUAL) {
        if (m0 >= g_cnt_pad[z]) return;
        int off = g_off_pad[z];
        ridx = g_tok_of_slot + off;
        A = g_hn_h; lda = CDIM;
        B1 = B1a + (size_t)z * FDIM * CDIM;
        B3 = B3a + (size_t)z * FDIM * CDIM;
        C = (void*)(g_hid_h + (size_t)off * FDIM); ldcx = FDIM;
    } else if (MODE == HP_EXPDOWN) {
        if (m0 >= g_cnt_pad[z]) return;
        int off = g_off_pad[z];
        A = g_hid_h + (size_t)off * FDIM; lda = FDIM;
        B1 = B1a + (size_t)z * CDIM * FDIM;
        C = (void*)(g_ctb + (size_t)off * CDIM); ldcx = CDIM;
        wrow = g_w_of_slot + off;
    }

    const int lane = tid & 31, warp = tid >> 5;
    const int wm = warp & 3, wn = warp >> 2;
    const int mw = wm * 32, nw = wn * (BN / 2);
    const int grp = lane >> 2, tig = lane & 3;

    const int KT = K >> 5;

    auto ISSUE = [&](int kt, int st) {
        if (kt < KT) {
            int k0 = kt << 5;
            #pragma unroll
            for (int t = 0; t < 2; t++) {
                int c = tid + 256 * t;
                int row = c >> 2, q = c & 3;
                int gr = (MODE == HP_EXPDUAL) ? ridx[m0 + row] : (m0 + row);
                cpa16(smem_u32(&sA[st * 128 * 40 + row * 40 + q * 8]),
                      A + (size_t)gr * lda + k0 + q * 8);
            }
            #pragma unroll
            for (int t = 0; t < BCH; t++) {
                int c = tid + 256 * t;
                int row = c >> 2, q = c & 3;
                cpa16(smem_u32(&sB1[st * BN * 40 + row * 40 + q * 8]),
                      B1 + (size_t)(n0 + row) * K + k0 + q * 8);
                if (DUAL)
                    cpa16(smem_u32(&sB3[st * BN * 40 + row * 40 + q * 8]),
                          B3 + (size_t)(n0 + row) * K + k0 + q * 8);
            }
        }
        CP_COMMIT();
    };

    float acc1[2][NT][4] = {};
    float acc3[2][DUAL ? NT : 1][4] = {};

    auto COMP = [&](int st) {
        const unsigned* uA  = (const unsigned*)(sA  + st * 128 * 40);
        const unsigned* uB1 = (const unsigned*)(sB1 + st * BN * 40);
        const unsigned* uB3 = (const unsigned*)(sB3 + st * BN * 40);
        #pragma unroll
        for (int s16 = 0; s16 < 2; s16++) {
            int ko = s16 * 8;
            unsigned bF1[NT][2], bF3[DUAL ? NT : 1][2], aF[2][4];
            #pragma unroll
            for (int j = 0; j < NT; j++) {
                int n = nw + j * 8 + grp;
                bF1[j][0] = uB1[n * 20 + ko + tig];
                bF1[j][1] = uB1[n * 20 + ko + 4 + tig];
                if (DUAL) {
                    bF3[j][0] = uB3[n * 20 + ko + tig];
                    bF3[j][1] = uB3[n * 20 + ko + 4 + tig];
                }
            }
            #pragma unroll
            for (int i = 0; i < 2; i++) {
                int m = mw + i * 16 + grp;
                aF[i][0] = uA[m * 20 + ko + tig];
                aF[i][1] = uA[(m + 8) * 20 + ko + tig];
                aF[i][2] = uA[m * 20 + ko + 4 + tig];
                aF[i][3] = uA[(m + 8) * 20 + ko + 4 + tig];
            }
            #pragma unroll
            for (int i = 0; i < 2; i++)
                #pragma unroll
                for (int j = 0; j < NT; j++) {
                    MMA_F16(acc1[i][j], aF[i], bF1[j]);
                    if (DUAL) MMA_F16(acc3[i][j], aF[i], bF3[j]);
                }
        }
    };

    ISSUE(0, 0);
    ISSUE(1, 1);
    for (int kt = 0; kt < KT; kt++) {
        int st = kt % 3;
        CP_WAIT1();
        __syncthreads();
        ISSUE(kt + 2, (kt + 2) % 3);
        COMP(st);
    }

    #pragma unroll
    for (int i = 0; i < 2; i++) {
        #pragma unroll
        for (int j = 0; j < NT; j++) {
            #pragma unroll
            for (int hh = 0; hh < 2; hh++) {
                int ml = mw + i * 16 + grp + hh * 8;
                int nl = nw + j * 8 + 2 * tig;
                float v0 = acc1[i][j][hh * 2 + 0];
                float v1 = acc1[i][j][hh * 2 + 1];
                int gm = m0 + ml, gn = n0 + nl;
                if (DUAL) {
                    v0 = v0 * siluf(acc3[i][j][hh * 2 + 0]);
                    v1 = v1 * siluf(acc3[i][j][hh * 2 + 1]);
                    *(__half2*)((__half*)C + (size_t)gm * ldcx + gn) = __floats2half2_rn(v0, v1);
                } else if (MODE == HP_EXPDOWN) {
                    float w = wrow[gm];
                    *(float2*)((float*)C + (size_t)gm * ldcx + gn) = make_float2(v0 * w, v1 * w);
                } else if (MODE == HP_RESID) {
                    float2 d = *(const float2*)(Da + (size_t)gm * ldcx + gn);
                    *(float2*)((float*)C + (size_t)gm * ldcx + gn) = make_float2(v0 + d.x, v1 + d.y);
                } else if (MODE == HP_QKV) {
                    if (gn < 1024)
                        *(__half2*)(g_q_h + (size_t)gm * 1024 + gn) =
                            __floats2half2_rn(v0 * 0.125f, v1 * 0.125f);
                    else
                        *(__half2*)(g_kv_h + (size_t)gm * 512 + gn - 1024) =
                            __floats2half2_rn(v0, v1);
                } else {  // HP_HALF
                    *(__half2*)((__half*)C + (size_t)gm * ldcx + gn) = __floats2half2_rn(v0, v1);
                }
            }
        }
    }
}

// ---------------- fp16 flash attention (online softmax) ----------------
#define FA_BYTES 91136

__global__ __launch_bounds__(256)
void k_flash_h(const __half* __restrict__ Qg, const __half* __restrict__ KVg,
               __half* __restrict__ Og)
{
    extern __shared__ __half fh[];
    __half* sQ  = fh;            // [128][72]
    __half* sK  = fh + 9216;     // [128][72]
    __half* sVt = fh + 18432;    // [64][136]  V transposed [d][s]
    __half* sP  = fh + 27136;    // [128][136]
    float* sRM = (float*)(fh + 44544);
    float* sRS = sRM + 256;
    const unsigned* uQ  = (const unsigned*)sQ;
    const unsigned* uK  = (const unsigned*)sK;
    const unsigned* uVt = (const unsigned*)sVt;
    unsigned* uP = (unsigned*)sP;

    const int qt = blockIdx.x, bh = blockIdx.y;
    const int b = bh >> 4, hh = bh & 15;
    const int tid = threadIdx.x, warp = tid >> 5, lane = tid & 31;
    const int wm = warp & 3, wn = warp >> 2;
    const int grp = lane >> 2, tig = lane & 3;
    const float NEG = -1e30f;

    const __half* Qb = Qg + (size_t)(b*1024 + qt*128) * 1024 + hh*64;
    #pragma unroll
    for (int t = 0; t < 4; t++) {
        int idx = tid + t*256;
        int r = idx >> 3, c = idx & 7;
        *(uint4*)&sQ[r*72 + c*8] = *(const uint4*)(Qb + (size_t)r*1024 + c*8);
    }

    float m_i[2][2] = {{NEG,NEG},{NEG,NEG}};
    float l_i[2][2] = {{0.f,0.f},{0.f,0.f}};
    float oacc[2][4][4] = {};

    for (int kt = 0; kt <= qt; kt++) {
        __syncthreads();
        const __half* KVb = KVg + (size_t)(b*1024 + kt*128) * 128;
        #pragma unroll
        for (int t = 0; t < 4; t++) {
            int idx = tid + t*256;
            int r = idx >> 3, c = idx & 7;
            *(uint4*)&sK[r*72 + c*8] = *(const uint4*)(KVb + (size_t)r*128 + c*8);
            uint4 vv = *(const uint4*)(KVb + (size_t)r*128 + 64 + c*8);
            __half tmp[8];
            memcpy(tmp, &vv, 16);
            #pragma unroll
            for (int i = 0; i < 8; i++)
                sVt[(c*8 + i)*136 + r] = tmp[i];
        }
        __syncthreads();

        // S = Q K^T (128x128, K=64) fp16 mma
        float sacc[2][8][4] = {};
        #pragma unroll
        for (int ks = 0; ks < 4; ks++) {
            int ko = ks * 8;
            unsigned aF[2][4], bF[8][2];
            #pragma unroll
            for (int j = 0; j < 8; j++) {
                int n = wn*64 + j*8 + grp;
                bF[j][0] = uK[n*36 + ko + tig];
                bF[j][1] = uK[n*36 + ko + 4 + tig];
            }
            #pragma unroll
            for (int i = 0; i < 2; i++) {
                int m = wm*32 + i*16 + grp;
                aF[i][0] = uQ[m*36 + ko + tig];
                aF[i][1] = uQ[(m+8)*36 + ko + tig];
                aF[i][2] = uQ[m*36 + ko + 4 + tig];
                aF[i][3] = uQ[(m+8)*36 + ko + 4 + tig];
            }
            #pragma unroll
            for (int i = 0; i < 2; i++)
                #pragma unroll
                for (int j = 0; j < 8; j++)
                    MMA_F16(sacc[i][j], aF[i], bF[j]);
        }

        if (kt == qt) {
            #pragma unroll
            for (int i = 0; i < 2; i++)
                #pragma unroll
                for (int h2 = 0; h2 < 2; h2++) {
                    int row = wm*32 + i*16 + grp + h2*8;
                    #pragma unroll
                    for (int j = 0; j < 8; j++) {
                        int col = wn*64 + j*8 + 2*tig;
                        if (col   > row) sacc[i][j][h2*2]   = NEG;
                        if (col+1 > row) sacc[i][j][h2*2+1] = NEG;
                    }
                }
        }

        #pragma unroll
        for (int i = 0; i < 2; i++)
            #pragma unroll
            for (int h2 = 0; h2 < 2; h2++) {
                float v = NEG;
                #pragma unroll
                for (int j = 0; j < 8; j++)
                    v = fmaxf(v, fmaxf(sacc[i][j][h2*2], sacc[i][j][h2*2+1]));
                v = fmaxf(v, __shfl_xor_sync(0xffffffffu, v, 1));
                v = fmaxf(v, __shfl_xor_sync(0xffffffffu, v, 2));
                if (tig == 0) sRM[wn*128 + wm*32 + i*16 + grp + h2*8] = v;
            }
        __syncthreads();

        #pragma unroll
        for (int i = 0; i < 2; i++)
            #pragma unroll
            for (int h2 = 0; h2 < 2; h2++) {
                int row = wm*32 + i*16 + grp + h2*8;
                float mnew = fmaxf(m_i[i][h2], fmaxf(sRM[row], sRM[128+row]));
                float fac = __expf(m_i[i][h2] - mnew);
                m_i[i][h2] = mnew;
                l_i[i][h2] *= fac;
                #pragma unroll
                for (int j = 0; j < 4; j++) {
                    oacc[i][j][h2*2]   *= fac;
                    oacc[i][j][h2*2+1] *= fac;
                }
                float rs = 0.0f;
                #pragma unroll
                for (int j = 0; j < 8; j++) {
                    float p0 = __expf(sacc[i][j][h2*2]   - mnew);
                    float p1 = __expf(sacc[i][j][h2*2+1] - mnew);
                    rs += p0 + p1;
                    int cu = wn*32 + j*4 + tig;   // uint col index (pair of halves)
                    uP[row*68 + cu] = h2_as_u32(__floats2half2_rn(p0, p1));
                }
                rs += __shfl_xor_sync(0xffffffffu, rs, 1);
                rs += __shfl_xor_sync(0xffffffffu, rs, 2);
                if (tig == 0) sRS[wn*128 + row] = rs;
            }
        __syncthreads();
        #pragma unroll
        for (int i = 0; i < 2; i++)
            #pragma unroll
            for (int h2 = 0; h2 < 2; h2++) {
                int row = wm*32 + i*16 + grp + h2*8;
                l_i[i][h2] += sRS[row] + sRS[128 + row];
            }

        // O += P (128x128) @ V (128x64) fp16 mma
        #pragma unroll
        for (int ks = 0; ks < 8; ks++) {
            int ko = ks * 8;
            unsigned aF[2][4], bF[4][2];
            #pragma unroll
            for (int j = 0; j < 4; j++) {
                int n = wn*32 + j*8 + grp;
                bF[j][0] = uVt[n*68 + ko + tig];
                bF[j][1] = uVt[n*68 + ko + 4 + tig];
            }
            #pragma unroll
            for (int i = 0; i < 2; i++) {
                int m = wm*32 + i*16 + grp;
                aF[i][0] = uP[m*68 + ko + tig];
                aF[i][1] = uP[(m+8)*68 + ko + tig];
                aF[i][2] = uP[m*68 + ko + 4 + tig];
                aF[i][3] = uP[(m+8)*68 + ko + 4 + tig];
            }
            #pragma unroll
            for (int i = 0; i < 2; i++)
                #pragma unroll
                for (int j = 0; j < 4; j++)
                    MMA_F16(oacc[i][j], aF[i], bF[j]);
        }
    }

    __half* Ob = Og + (size_t)(b*1024 + qt*128) * 1024 + hh*64;
    #pragma unroll
    for (int i = 0; i < 2; i++)
        #pragma unroll
        for (int h2 = 0; h2 < 2; h2++) {
            int row = wm*32 + i*16 + grp + h2*8;
            float inv = 1.0f / l_i[i][h2];
            #pragma unroll
            for (int j = 0; j < 4; j++) {
                int col = wn*32 + j*8 + 2*tig;
                *(__half2*)(Ob + (size_t)row*1024 + col) =
                    __floats2half2_rn(oacc[i][j][h2*2]*inv, oacc[i][j][h2*2+1]*inv);
            }
        }
}

// ---------------- elementwise / small kernels ----------------
__global__ __launch_bounds__(256)
void k_rmsnorm(const float* __restrict__ X, const float* __restrict__ G,
               float* __restrict__ Of, __half* __restrict__ Oh)
{
    int n = blockIdx.x;
    const float4* x4 = (const float4*)(X + (size_t)n * CDIM);
    const float4* g4 = (const float4*)G;
    float4 v = x4[threadIdx.x];
    float ss = v.x*v.x + v.y*v.y + v.z*v.z + v.w*v.w;
    float tot = block_reduce_sum256(ss);
    float r = 1.0f / sqrtf(tot * (1.0f / CDIM) + 1e-6f);
    float4 g = g4[threadIdx.x];
    float4 full = make_float4(v.x*r*g.x, v.y*r*g.y, v.z*r*g.z, v.w*r*g.w);
    if (Of) ((float4*)(Of + (size_t)n * CDIM))[threadIdx.x] = full;
    if (Oh) {
        *(__half2*)(Oh + (size_t)n * CDIM + threadIdx.x * 4)     = __floats2half2_rn(full.x, full.y);
        *(__half2*)(Oh + (size_t)n * CDIM + threadIdx.x * 4 + 2) = __floats2half2_rn(full.z, full.w);
    }
}

__global__ __launch_bounds__(128)
void k_router(const float* __restrict__ HN, const float* __restrict__ WR,
              const float* __restrict__ RB)
{
    int n = blockIdx.x * 4 + (threadIdx.x >> 5);
    int lane = threadIdx.x & 31;
    const float* x = HN + (size_t)n * CDIM;
    float p[NEXP] = {};
    for (int c = lane; c < CDIM; c += 32) {
        float xv = x[c];
        #pragma unroll
        for (int e = 0; e < NEXP; e++) p[e] += xv * WR[c * NEXP + e];
    }
    #pragma unroll
    for (int e = 0; e < NEXP; e++) {
        #pragma unroll
        for (int o = 16; o; o >>= 1)
            p[e] += __shfl_xor_sync(0xffffffffu, p[e], o);
    }
    if (lane == 0) {
        float logit[NEXP], biased[NEXP];
        #pragma unroll
        for (int e = 0; e < NEXP; e++) {
            logit[e]  = p[e] * 0.03125f;
            biased[e] = logit[e] + RB[e];
        }
        int i0 = 0;
        #pragma unroll
        for (int e = 1; e < NEXP; e++) if (biased[e] > biased[i0]) i0 = e;
        int i1 = -1;
        #pragma unroll
        for (int e = 0; e < NEXP; e++) {
            if (e == i0) continue;
            if (i1 < 0 || biased[e] > biased[i1]) i1 = e;
        }
        float m  = fmaxf(logit[i0], logit[i1]);
        float e0 = expf(logit[i0] - m), e1 = expf(logit[i1] - m);
        float inv = 1.0f / (e0 + e1);
        g_top [n*2]     = i0; g_top [n*2 + 1] = i1;
        g_topw[n*2]     = e0 * inv;
        g_topw[n*2 + 1] = e1 * inv;
    }
}

__global__ __launch_bounds__(256)
void k_place()
{
    __shared__ int cnt[NEXP], offp[NEXP], cntp[NEXP], cur[NEXP];
    int tid = threadIdx.x;
    if (tid < NEXP) cnt[tid] = 0;
    __syncthreads();
    for (int i = tid; i < NTOK * 2; i += 256) atomicAdd(&cnt[g_top[i]], 1);
    __syncthreads();
    if (tid == 0) {
        int o = 0;
        for (int e = 0; e < NEXP; e++) {
            offp[e] = o;
            cntp[e] = ((cnt[e] + 127) >> 7) << 7;
            cur[e]  = o;
            g_off_pad[e] = o;
            g_cnt_pad[e] = cntp[e];
            o += cntp[e];
        }
    }
    __syncthreads();
    for (int i = tid; i < NTOK * 2; i += 256) {
        int e = g_top[i];
        int s = atomicAdd(&cur[e], 1);
        g_tok_of_slot[s] = i >> 1;
        g_w_of_slot[s]   = g_topw[i];
        g_slot_of_tok[i] = s;
    }
    __syncthreads();
    for (int e = 0; e < NEXP; e++) {
        int start = offp[e] + cnt[e];
        int end   = offp[e] + cntp[e];
        for (int i = start + tid; i < end; i += 256) {
            g_tok_of_slot[i] = 0;
            g_w_of_slot[i]   = 0.0f;
        }
    }
}

__global__ __launch_bounds__(256)
void k_combine(const float* __restrict__ SOUT, const float* __restrict__ CT,
               float* __restrict__ OUT)
{
    int n = blockIdx.x;
    int s0 = g_slot_of_tok[n*2], s1 = g_slot_of_tok[n*2 + 1];
    const float4* a  = (const float4*)(SOUT + (size_t)n  * CDIM);
    const float4* c0 = (const float4*)(CT   + (size_t)s0 * CDIM);
    const float4* c1 = (const float4*)(CT   + (size_t)s1 * CDIM);
    float4* o = (float4*)(OUT + (size_t)n * CDIM);
    int i = threadIdx.x;
    float4 va = a[i], v0 = c0[i], v1 = c1[i];
    o[i] = make_float4(va.x + v0.x + v1.x, va.y + v0.y + v1.y,
                       va.z + v0.z + v1.z, va.w + v0.w + v1.w);
}

// ---------------- launch ----------------
extern "C" void kernel_launch(void* const* d_in, const int* in_sizes, int n_in,
                              void* d_out, int out_size)
{
    const float* x    = (const float*)d_in[0];
    const float* ga   = (const float*)d_in[1];
    const float* wq   = (const float*)d_in[2];
    const float* wkvd = (const float*)d_in[3];
    const float* wku  = (const float*)d_in[4];
    const float* wvu  = (const float*)d_in[5];
    const float* wo   = (const float*)d_in[6];
    const float* gm   = (const float*)d_in[7];
    const float* wr   = (const float*)d_in[8];
    const float* rb   = (const float*)d_in[9];
    const float* ew1  = (const float*)d_in[10];
    const float* ew2  = (const float*)d_in[11];
    const float* ew3  = (const float*)d_in[12];
    const float* sw1  = (const float*)d_in[13];
    const float* sw2  = (const float*)d_in[14];
    const float* sw3  = (const float*)d_in[15];
    float* out = (float*)d_out;

    float *hb, *hnf, *ctb, *sout;
    __half *xn_h, *q_h, *kv_h, *kvo_h, *att_h, *hn_h, *hid_h, *shid_h;
    __half *wqkv_h, *wkv_h, *wo_h, *sw1_h, *sw3_h, *sw2_h, *ew1_h, *ew2_h, *ew3_h;
    cudaGetSymbolAddress((void**)&hb,   g_h);
    cudaGetSymbolAddress((void**)&hnf,  g_hnf);
    cudaGetSymbolAddress((void**)&ctb,  g_ctb);
    cudaGetSymbolAddress((void**)&sout, g_sout);
    cudaGetSymbolAddress((void**)&xn_h,  g_xn_h);
    cudaGetSymbolAddress((void**)&q_h,   g_q_h);
    cudaGetSymbolAddress((void**)&kv_h,  g_kv_h);
    cudaGetSymbolAddress((void**)&kvo_h, g_kvo_h);
    cudaGetSymbolAddress((void**)&att_h, g_att_h);
    cudaGetSymbolAddress((void**)&hn_h,  g_hn_h);
    cudaGetSymbolAddress((void**)&hid_h, g_hid_h);
    cudaGetSymbolAddress((void**)&shid_h, g_shid_h);
    cudaGetSymbolAddress((void**)&wqkv_h, g_wqkv_h);
    cudaGetSymbolAddress((void**)&wkv_h,  g_wkv_h);
    cudaGetSymbolAddress((void**)&wo_h,   g_wo_h);
    cudaGetSymbolAddress((void**)&sw1_h,  g_sw1_h);
    cudaGetSymbolAddress((void**)&sw3_h,  g_sw3_h);
    cudaGetSymbolAddress((void**)&sw2_h,  g_sw2_h);
    cudaGetSymbolAddress((void**)&ew1_h,  g_ew1_h);
    cudaGetSymbolAddress((void**)&ew2_h,  g_ew2_h);
    cudaGetSymbolAddress((void**)&ew3_h,  g_ew3_h);

    cudaFuncSetAttribute(k_flash_h, cudaFuncAttributeMaxDynamicSharedMemorySize, FA_BYTES);
    cudaFuncSetAttribute(gemm_hp<HP_DUAL,64>,     cudaFuncAttributeMaxDynamicSharedMemorySize, SMHP);
    cudaFuncSetAttribute(gemm_hp<HP_EXPDUAL,64>,  cudaFuncAttributeMaxDynamicSharedMemorySize, SMHP);
    cudaFuncSetAttribute(gemm_hp<HP_EXPDOWN,128>, cudaFuncAttributeMaxDynamicSharedMemorySize, SMHP);
    cudaFuncSetAttribute(gemm_hp<HP_RESID,128>,   cudaFuncAttributeMaxDynamicSharedMemorySize, SMHP);
    cudaFuncSetAttribute(gemm_hp<HP_QKV,128>,     cudaFuncAttributeMaxDynamicSharedMemorySize, SMHP);
    cudaFuncSetAttribute(gemm_hp<HP_HALF,128>,    cudaFuncAttributeMaxDynamicSharedMemorySize, SMHP);

    // ---- weight prep: convert + transpose to [N][K] half ----
    k_cvt_tr<<<dim3(32, 32), 256>>>(wq,   wqkv_h,               1024, 1024);
    k_cvt_tr<<<dim3(16, 32), 256>>>(wkvd, wqkv_h + 1024*1024,   1024, 512);
    k_cvt_tr<<<dim3(2, 16), 256>>>(wku,  wkv_h,                512,  64);
    k_cvt_tr<<<dim3(2, 16), 256>>>(wvu,  wkv_h + 64*512,       512,  64);
    k_cvt_tr<<<dim3(32, 32), 256>>>(wo,   wo_h,                 1024, 1024);
    k_cvt_tr<<<dim3(32, 32, NEXP), 256>>>(ew1, ew1_h, CDIM, FDIM);
    k_cvt_tr<<<dim3(32, 32, NEXP), 256>>>(ew3, ew3_h, CDIM, FDIM);
    k_cvt_tr<<<dim3(32, 32, NEXP), 256>>>(ew2, ew2_h, FDIM, CDIM);
    k_cvt_tr<<<dim3(64, 32), 256>>>(sw1, sw1_h, CDIM, FSH);
    k_cvt_tr<<<dim3(64, 32), 256>>>(sw3, sw3_h, CDIM, FSH);
    k_cvt_tr<<<dim3(32, 64), 256>>>(sw2, sw2_h, FSH, CDIM);

    // ---- attention (fp16) ----
    k_rmsnorm<<<NTOK, 256>>>(x, ga, nullptr, xn_h);
    gemm_hp<HP_QKV,128><<<dim3(12, 32), 256, SMHP>>>(xn_h, 1024, wqkv_h, nullptr, nullptr, 0, nullptr, 1024);
    gemm_hp<HP_HALF,128><<<dim3(1, 32), 256, SMHP>>>(kv_h, 512, wkv_h, nullptr, kvo_h, 128, nullptr, 512);
    k_flash_h<<<dim3(8, 64), 256, FA_BYTES>>>(q_h, kvo_h, att_h);
    gemm_hp<HP_RESID,128><<<dim3(8, 32), 256, SMHP>>>(att_h, 1024, wo_h, nullptr, hb, 1024, x, 1024);

    // ---- MoE (fp16) ----
    k_rmsnorm<<<NTOK, 256>>>(hb, gm, hnf, hn_h);
    k_router<<<NTOK/4, 128>>>(hnf, wr, rb);
    k_place<<<1, 256>>>();
    gemm_hp<HP_EXPDUAL,64><<<dim3(16, 72, NEXP), 256, SMHP>>>(nullptr, 0, ew1_h, ew3_h, nullptr, 0, nullptr, 1024);
    gemm_hp<HP_EXPDOWN,128><<<dim3(8, 72, NEXP), 256, SMHP>>>(nullptr, 0, ew2_h, nullptr, nullptr, 0, nullptr, 1024);
    gemm_hp<HP_DUAL,64><<<dim3(32, 32), 256, SMHP>>>(hn_h, 1024, sw1_h, sw3_h, shid_h, 2048, nullptr, 1024);
    gemm_hp<HP_RESID,128><<<dim3(8, 32), 256, SMHP>>>(shid_h, 2048, sw2_h, nullptr, sout, 1024, hb, 2048);
    k_combine<<<NTOK, 256>>>(sout, ctb, out);
}